// round 1
// baseline (speedup 1.0000x reference)
#include <cuda_runtime.h>
#include <cstdint>

#define NG 64
#define NC 32
#define LL 128
#define DD 64
#define HH 128
#define NCLASS 10
#define BTOT 2048          // G*C
#define NGATES 512         // 4*H

#define CL_BT 28           // batches per 2-CTA cluster (74 clusters cover 2072 >= 2048)
#define LSTM_THREADS 224   // 7 warps: warp = 4 batches, lane = column group

// Scratch (allocation-free rule: __device__ globals)
__device__ float g_xg[(size_t)LL * BTOT * NGATES];  // [t][b][gate]  (gate = torch i|f|g|o rows)
__device__ float g_rep[BTOT * HH];                  // sum_t h

__device__ __forceinline__ float sigf(float x) {
    return __fdividef(1.0f, 1.0f + __expf(-x));
}
__device__ __forceinline__ float tanh_f(float x) {
    return 2.0f * __fdividef(1.0f, 1.0f + __expf(-2.0f * x)) - 1.0f;
}

// ============================================================================
// Kernel 1: xg[t][b][g] = (b_ih+b_hh)[g] + sum_d x[b][t][d] * W_ih[g][d]
// Tokens are (b,t) pairs, contiguous in x. Each CTA: W_ih^T in smem (128KB),
// grid-stride over 32-token tiles; thread computes 4 tokens x 16 gate-cols.
// ============================================================================
__global__ void __launch_bounds__(256, 1)
xg_kernel(const float* __restrict__ x, const float* __restrict__ W_ih,
          const float* __restrict__ b_ih, const float* __restrict__ b_hh) {
    extern __shared__ float sm[];
    float* Wt = sm;                 // [DD][NGATES] transposed: Wt[d*512+g]
    float* xs = sm + DD * NGATES;   // [32][DD]
    int tid = threadIdx.x;
    for (int idx = tid; idx < NGATES * DD; idx += 256) {
        int g = idx >> 6, d = idx & 63;
        Wt[d * NGATES + g] = W_ih[idx];
    }
    int lane = tid & 31;
    int jt = tid >> 5;              // token-quad index [0,8)
    float bias[16];
#pragma unroll
    for (int q = 0; q < 16; q++) {
        int g = lane + 32 * q;
        bias[q] = b_ih[g] + b_hh[g];
    }
    __syncthreads();

    const int niters = (BTOT * LL) / 32;  // 8192
    for (int it = blockIdx.x; it < niters; it += gridDim.x) {
        int tok0 = it * 32;
        __syncthreads();  // WAR on xs from previous iter
        for (int idx = tid; idx < 32 * DD; idx += 256)
            xs[idx] = x[(size_t)tok0 * DD + idx];
        __syncthreads();

        float acc[4][16];
#pragma unroll
        for (int ti = 0; ti < 4; ti++)
#pragma unroll
            for (int q = 0; q < 16; q++) acc[ti][q] = bias[q];

        for (int d = 0; d < DD; d += 4) {
            float4 xv[4];
#pragma unroll
            for (int ti = 0; ti < 4; ti++)
                xv[ti] = *(const float4*)&xs[(jt * 4 + ti) * DD + d];
#pragma unroll
            for (int dd = 0; dd < 4; dd++) {
                float w[16];
#pragma unroll
                for (int q = 0; q < 16; q++)
                    w[q] = Wt[(d + dd) * NGATES + lane + 32 * q];
#pragma unroll
                for (int ti = 0; ti < 4; ti++) {
                    float xvv = (dd == 0) ? xv[ti].x : (dd == 1) ? xv[ti].y
                              : (dd == 2) ? xv[ti].z : xv[ti].w;
#pragma unroll
                    for (int q = 0; q < 16; q++)
                        acc[ti][q] = fmaf(xvv, w[q], acc[ti][q]);
                }
            }
        }
#pragma unroll
        for (int ti = 0; ti < 4; ti++) {
            int tok = tok0 + jt * 4 + ti;
            int b = tok >> 7, t = tok & 127;
            float* dst = &g_xg[((size_t)t * BTOT + b) * NGATES];
#pragma unroll
            for (int q = 0; q < 16; q++)
                dst[lane + 32 * q] = acc[ti][q];
        }
    }
}

// ============================================================================
// Kernel 2: recurrent LSTM. 2-CTA cluster; rank r owns hidden units
// [r*64, r*64+64) (all 4 gates). W half transposed in smem (128KB);
// h (full 128) double-buffered in smem, halves exchanged via st.shared::cluster
// + barrier.cluster each step. c-state and sum_t h live in registers.
// Thread (warp w, lane l): batches b0+4w..+4, columns c = l + 32*j (j<8):
//   j: 0=i(A) 1=i(B) 2=f(A) 3=f(B) 4=g(A) 5=g(B) 6=o(A) 7=o(B),
//   unit A = l, unit B = l+32 (local), global unit = r*64 + local.
// ============================================================================
__global__ void __launch_bounds__(LSTM_THREADS, 1) __cluster_dims__(2, 1, 1)
lstm_kernel(const float* __restrict__ W_hh) {
    extern __shared__ float sm[];
    float* Wt   = sm;               // [HH][256]: Wt[m*256 + c] = W_hh[row(c)][m]
    float* hbuf = sm + HH * 256;    // [2][CL_BT][HH]

    int tid = threadIdx.x;
    uint32_t rank;
    asm("mov.u32 %0, %%cluster_ctarank;" : "=r"(rank));
    int cid = blockIdx.x >> 1;
    int b0 = cid * CL_BT;
    int lane = tid & 31, wrp = tid >> 5;  // wrp in [0,7)

    // Load this CTA's W half, transposed (one-time; STS conflicts are amortized)
    for (int idx = tid; idx < 256 * HH; idx += LSTM_THREADS) {
        int c = idx >> 7, m = idx & 127;
        int row = ((c >> 6) * HH) + (int)rank * 64 + (c & 63);
        Wt[m * 256 + c] = W_hh[row * HH + m];
    }
    for (int idx = tid; idx < CL_BT * HH; idx += LSTM_THREADS)
        hbuf[idx] = 0.0f;   // h_0 = 0 (buffer 0)
    __syncthreads();
    asm volatile("barrier.cluster.arrive.aligned;" ::: "memory");
    asm volatile("barrier.cluster.wait.aligned;" ::: "memory");

    // Peer smem base for remote h pushes
    uint32_t smem_local;
    asm("{ .reg .u64 t0; cvta.to.shared.u64 t0, %1; cvt.u32.u64 %0, t0; }"
        : "=r"(smem_local) : "l"(sm));
    uint32_t smem_peer;
    asm("mapa.shared::cluster.u32 %0, %1, %2;"
        : "=r"(smem_peer) : "r"(smem_local), "r"(rank ^ 1u));
    uint32_t hbuf_peer = smem_peer + (uint32_t)(HH * 256 * 4);

    int rowoff[8];
#pragma unroll
    for (int j = 0; j < 8; j++) {
        int c = lane + 32 * j;
        rowoff[j] = ((c >> 6) * HH) + (int)rank * 64 + (c & 63);
    }
    int bidx[4];
#pragma unroll
    for (int bi = 0; bi < 4; bi++) {
        int b = b0 + wrp * 4 + bi;
        bidx[bi] = (b < BTOT) ? b : (BTOT - 1);  // clamp loads; stores guarded
    }

    float cst[8], hsum[8];
#pragma unroll
    for (int k = 0; k < 8; k++) { cst[k] = 0.f; hsum[k] = 0.f; }

    int cur = 0;
#pragma unroll 1
    for (int t = 0; t < LL; t++) {
        // xg loads (coalesced per (bi,j)); consumed only after GEMM -> latency hidden
        float xv[4][8];
#pragma unroll
        for (int bi = 0; bi < 4; bi++) {
            const float* src = &g_xg[((size_t)t * BTOT + bidx[bi]) * NGATES];
#pragma unroll
            for (int j = 0; j < 8; j++) xv[bi][j] = src[rowoff[j]];
        }

        const float* hc = hbuf + cur * (CL_BT * HH);
        float acc[4][8];
#pragma unroll
        for (int bi = 0; bi < 4; bi++)
#pragma unroll
            for (int j = 0; j < 8; j++) acc[bi][j] = 0.f;

#pragma unroll 4
        for (int m = 0; m < HH; m += 4) {
            float4 hv[4];
#pragma unroll
            for (int bi = 0; bi < 4; bi++)
                hv[bi] = *(const float4*)&hc[(wrp * 4 + bi) * HH + m];  // warp-broadcast
#pragma unroll
            for (int mm = 0; mm < 4; mm++) {
                float w[8];
#pragma unroll
                for (int j = 0; j < 8; j++)
                    w[j] = Wt[(m + mm) * 256 + lane + 32 * j];  // conflict-free
#pragma unroll
                for (int bi = 0; bi < 4; bi++) {
                    float h = (mm == 0) ? hv[bi].x : (mm == 1) ? hv[bi].y
                            : (mm == 2) ? hv[bi].z : hv[bi].w;
#pragma unroll
                    for (int j = 0; j < 8; j++)
                        acc[bi][j] = fmaf(h, w[j], acc[bi][j]);
                }
            }
        }

        int nxt = cur ^ 1;
        float* hn = hbuf + nxt * (CL_BT * HH);
        uint32_t hn_peer = hbuf_peer + (uint32_t)(nxt * CL_BT * HH * 4);
#pragma unroll
        for (int bi = 0; bi < 4; bi++) {
            float iA = sigf(acc[bi][0] + xv[bi][0]);
            float iB = sigf(acc[bi][1] + xv[bi][1]);
            float fA = sigf(acc[bi][2] + xv[bi][2]);
            float fB = sigf(acc[bi][3] + xv[bi][3]);
            float gA = tanh_f(acc[bi][4] + xv[bi][4]);
            float gB = tanh_f(acc[bi][5] + xv[bi][5]);
            float oA = sigf(acc[bi][6] + xv[bi][6]);
            float oB = sigf(acc[bi][7] + xv[bi][7]);
            float cA = fmaf(fA, cst[bi * 2], iA * gA);
            float cB = fmaf(fB, cst[bi * 2 + 1], iB * gB);
            cst[bi * 2] = cA;
            cst[bi * 2 + 1] = cB;
            float hA = oA * tanh_f(cA);
            float hB = oB * tanh_f(cB);
            hsum[bi * 2] += hA;
            hsum[bi * 2 + 1] += hB;
            int posA = (wrp * 4 + bi) * HH + (int)rank * 64 + lane;
            hn[posA] = hA;
            hn[posA + 32] = hB;
            uint32_t pa = hn_peer + (uint32_t)(posA * 4);
            asm volatile("st.shared::cluster.f32 [%0], %1;" :: "r"(pa), "f"(hA) : "memory");
            asm volatile("st.shared::cluster.f32 [%0], %1;" :: "r"(pa + 128), "f"(hB) : "memory");
        }
        // release/acquire: orders local STS + remote st.shared::cluster vs next-step reads
        asm volatile("barrier.cluster.arrive.aligned;" ::: "memory");
        asm volatile("barrier.cluster.wait.aligned;" ::: "memory");
        cur = nxt;
    }

#pragma unroll
    for (int bi = 0; bi < 4; bi++) {
        int b = b0 + wrp * 4 + bi;
        if (b < BTOT) {
            g_rep[b * HH + (int)rank * 64 + lane]      = hsum[bi * 2];
            g_rep[b * HH + (int)rank * 64 + lane + 32] = hsum[bi * 2 + 1];
        }
    }
}

// ============================================================================
// Kernel 3: per-graph mean over cycles, classifier, log_softmax. Tiny.
// ============================================================================
__global__ void cls_kernel(const float* __restrict__ W_cls, const float* __restrict__ b_cls,
                           float* __restrict__ out) {
    __shared__ float mean_s[HH];
    __shared__ float lg[NCLASS];
    int g = blockIdx.x, tid = threadIdx.x;
    float s = 0.f;
    for (int c = 0; c < NC; c++)
        s += g_rep[(g * NC + c) * HH + tid];
    mean_s[tid] = s * (1.0f / NC);
    __syncthreads();
    if (tid < NCLASS) {
        float d = b_cls[tid];
        for (int h = 0; h < HH; h++)
            d = fmaf(mean_s[h], W_cls[tid * HH + h], d);
        lg[tid] = d;
    }
    __syncthreads();
    if (tid == 0) {
        float mx = lg[0];
        for (int n = 1; n < NCLASS; n++) mx = fmaxf(mx, lg[n]);
        float sum = 0.f;
        for (int n = 0; n < NCLASS; n++) sum += expf(lg[n] - mx);
        float l = logf(sum);
        for (int n = 0; n < NCLASS; n++)
            out[g * NCLASS + n] = lg[n] - mx - l;
    }
}

extern "C" void kernel_launch(void* const* d_in, const int* in_sizes, int n_in,
                              void* d_out, int out_size) {
    (void)in_sizes; (void)n_in; (void)out_size;
    const float* x     = (const float*)d_in[0];  // cycle_reps [64,32,128,64]
    const float* W_ih  = (const float*)d_in[1];  // [512,64]
    const float* W_hh  = (const float*)d_in[2];  // [512,128]
    const float* b_ih  = (const float*)d_in[3];  // [512]
    const float* b_hh  = (const float*)d_in[4];  // [512]
    const float* W_cls = (const float*)d_in[5];  // [10,128]
    const float* b_cls = (const float*)d_in[6];  // [10]

    int smem1 = (DD * NGATES + 32 * DD) * (int)sizeof(float);          // 139264 B
    int smem2 = (HH * 256 + 2 * CL_BT * HH) * (int)sizeof(float);      // 159744 B
    cudaFuncSetAttribute(xg_kernel, cudaFuncAttributeMaxDynamicSharedMemorySize, smem1);
    cudaFuncSetAttribute(lstm_kernel, cudaFuncAttributeMaxDynamicSharedMemorySize, smem2);

    xg_kernel<<<148, 256, smem1>>>(x, W_ih, b_ih, b_hh);
    lstm_kernel<<<148, LSTM_THREADS, smem2>>>(W_hh);   // 74 clusters of 2
    cls_kernel<<<NG, HH>>>(W_cls, b_cls, (float*)d_out);
}

// round 2
// speedup vs baseline: 1.2563x; 1.2563x over previous
#include <cuda_runtime.h>
#include <cstdint>

#define NG 64
#define NC 32
#define LL 128
#define DD 64
#define HH 128
#define NCLASS 10
#define BTOT 2048          // G*C
#define NGATES 512         // 4*H

#define CL_BT 28           // batches per 2-CTA cluster (74 clusters cover 2072 >= 2048)
#define LSTM_THREADS 128   // 4 warps; warp = 7 batches, lane = unit-pair
#define BPT 7              // batches per thread (per warp)

// Scratch (allocation-free rule: __device__ globals)
__device__ float g_xg[(size_t)LL * BTOT * NGATES];  // [t][b][gate]  (gate = torch i|f|g|o rows)
__device__ float g_rep[BTOT * HH];                  // sum_t h

typedef unsigned long long u64;

// packed f32x2 helpers (FFMA2 — ptxas never auto-fuses; PTX-only per SASS_QUICKREF)
#define FMA2(d, a, b, c) \
    asm("fma.rn.f32x2 %0, %1, %2, %3;" : "=l"(d) : "l"(a), "l"(b), "l"(c))
#define ADD2(d, a, b) \
    asm("add.rn.f32x2 %0, %1, %2;" : "=l"(d) : "l"(a), "l"(b))
#define PACK_DUP(d, f) \
    asm("mov.b64 %0, {%1, %1};" : "=l"(d) : "r"(__float_as_uint(f)))
#define PACK2(d, lo, hi) \
    asm("mov.b64 %0, {%1, %2};" : "=l"(d) : "r"(__float_as_uint(lo)), "r"(__float_as_uint(hi)))
#define UNPACK2(lo, hi, v) do { unsigned _ul, _uh;                         \
    asm("mov.b64 {%0, %1}, %2;" : "=r"(_ul), "=r"(_uh) : "l"(v));          \
    lo = __uint_as_float(_ul); hi = __uint_as_float(_uh); } while (0)

__device__ __forceinline__ float sigf(float x) {
    return __fdividef(1.0f, 1.0f + __expf(-x));
}
__device__ __forceinline__ float tanh_f(float x) {
    return 2.0f * __fdividef(1.0f, 1.0f + __expf(-2.0f * x)) - 1.0f;
}

// ============================================================================
// Kernel 1: xg[t][b][g] = (b_ih+b_hh)[g] + sum_d x[b][t][d] * W_ih[g][d]
// Thread covers 4 tokens x 8 gate-PAIRS (g = 2*lane + 64*q). W pairs via
// LDS.64; MACs via fma.rn.f32x2 (half the FFMA issues of round 1).
// ============================================================================
__global__ void __launch_bounds__(256, 1)
xg_kernel(const float* __restrict__ x, const float* __restrict__ W_ih,
          const float* __restrict__ b_ih, const float* __restrict__ b_hh) {
    extern __shared__ float sm[];
    float* Wt = sm;                 // [DD][NGATES] transposed: Wt[d*512+g]
    float* xs = sm + DD * NGATES;   // [32][DD]
    int tid = threadIdx.x;
    for (int idx = tid; idx < NGATES * DD; idx += 256) {
        int g = idx >> 6, d = idx & 63;
        Wt[d * NGATES + g] = W_ih[idx];
    }
    int lane = tid & 31;
    int jt = tid >> 5;              // token-quad index [0,8)
    u64 bias2[8];
#pragma unroll
    for (int q = 0; q < 8; q++) {
        int g = 2 * lane + 64 * q;
        PACK2(bias2[q], b_ih[g] + b_hh[g], b_ih[g + 1] + b_hh[g + 1]);
    }
    __syncthreads();

    const int niters = (BTOT * LL) / 32;  // 8192
    for (int it = blockIdx.x; it < niters; it += gridDim.x) {
        int tok0 = it * 32;
        __syncthreads();  // WAR on xs from previous iter
        for (int idx = tid; idx < 32 * DD; idx += 256)
            xs[idx] = x[(size_t)tok0 * DD + idx];
        __syncthreads();

        u64 acc2[4][8];
#pragma unroll
        for (int ti = 0; ti < 4; ti++)
#pragma unroll
            for (int q = 0; q < 8; q++) acc2[ti][q] = bias2[q];

        for (int d = 0; d < DD; d += 4) {
            float4 xv[4];
#pragma unroll
            for (int ti = 0; ti < 4; ti++)
                xv[ti] = *(const float4*)&xs[(jt * 4 + ti) * DD + d];
#pragma unroll
            for (int dd = 0; dd < 4; dd++) {
                u64 w2[8];
#pragma unroll
                for (int q = 0; q < 8; q++)
                    w2[q] = *(const u64*)&Wt[(d + dd) * NGATES + 2 * lane + 64 * q];
#pragma unroll
                for (int ti = 0; ti < 4; ti++) {
                    float xvv = (dd == 0) ? xv[ti].x : (dd == 1) ? xv[ti].y
                              : (dd == 2) ? xv[ti].z : xv[ti].w;
                    u64 x2; PACK_DUP(x2, xvv);
#pragma unroll
                    for (int q = 0; q < 8; q++)
                        FMA2(acc2[ti][q], x2, w2[q], acc2[ti][q]);
                }
            }
        }
#pragma unroll
        for (int ti = 0; ti < 4; ti++) {
            int tok = tok0 + jt * 4 + ti;
            int b = tok >> 7, t = tok & 127;
            float* dst = &g_xg[((size_t)t * BTOT + b) * NGATES];
#pragma unroll
            for (int q = 0; q < 8; q++)
                *(u64*)&dst[2 * lane + 64 * q] = acc2[ti][q];
        }
    }
}

// ============================================================================
// Kernel 2: recurrent LSTM. 2-CTA cluster; rank r owns hidden units
// [r*64, r*64+64). 4 warps x 7 batches/thread. Thread (lane l) owns local
// unit pair (2l, 2l+1) for ALL 4 gates: col pair p -> gate p, units 2l,2l+1.
// W pairs via LDS.64 feed fma.rn.f32x2; h duplicated via mov.b64 {h,h}.
// xg preactivations for step t are loaded at step start (gmem), consumed only
// in the epilogue -> latency hidden by the GEMM. Cluster barrier split
// (arrive at step end, wait after next step's loads).
// ============================================================================
__global__ void __launch_bounds__(LSTM_THREADS, 1) __cluster_dims__(2, 1, 1)
lstm_kernel(const float* __restrict__ W_hh) {
    extern __shared__ float sm[];
    float* Wt   = sm;               // [HH][256]: Wt[m*256 + c] = W_hh[row(c)][m]
    float* hbuf = sm + HH * 256;    // [2][CL_BT][HH]

    int tid = threadIdx.x;
    uint32_t rank;
    asm("mov.u32 %0, %%cluster_ctarank;" : "=r"(rank));
    int cid = blockIdx.x >> 1;
    int b0 = cid * CL_BT;
    int lane = tid & 31, wrp = tid >> 5;  // wrp in [0,4)

    // Load this CTA's W half, transposed (one-time cost)
    for (int idx = tid; idx < 256 * HH; idx += LSTM_THREADS) {
        int c = idx >> 7, m = idx & 127;
        int row = ((c >> 6) * HH) + (int)rank * 64 + (c & 63);
        Wt[m * 256 + c] = W_hh[row * HH + m];
    }
    for (int idx = tid; idx < 2 * CL_BT * HH; idx += LSTM_THREADS)
        hbuf[idx] = 0.0f;   // h_0 = 0
    __syncthreads();

    // Peer smem base for remote h pushes
    uint32_t smem_local;
    asm("{ .reg .u64 t0; cvta.to.shared.u64 t0, %1; cvt.u32.u64 %0, t0; }"
        : "=r"(smem_local) : "l"(sm));
    uint32_t smem_peer;
    asm("mapa.shared::cluster.u32 %0, %1, %2;"
        : "=r"(smem_peer) : "r"(smem_local), "r"(rank ^ 1u));
    uint32_t hbuf_peer = smem_peer + (uint32_t)(HH * 256 * 4);

    const float* xsrc[BPT];
#pragma unroll
    for (int bi = 0; bi < BPT; bi++) {
        int b = b0 + wrp * BPT + bi;
        if (b >= BTOT) b = BTOT - 1;           // clamp loads; stores guarded
        xsrc[bi] = &g_xg[(size_t)b * NGATES + (int)rank * 64 + 2 * lane];
    }
    const int colbase = 2 * lane;

    float cst[2 * BPT], hsum[2 * BPT];
#pragma unroll
    for (int k = 0; k < 2 * BPT; k++) { cst[k] = 0.f; hsum[k] = 0.f; }

    // phase 0 arrive (matches wait at top of first iteration)
    asm volatile("barrier.cluster.arrive.aligned;" ::: "memory");

    int cur = 0;
#pragma unroll 1
    for (int t = 0; t < LL; t++) {
        // issue xg loads for this step (gmem only; before the barrier wait)
        u64 xv2[BPT][4];
#pragma unroll
        for (int bi = 0; bi < BPT; bi++) {
            const float* src = xsrc[bi] + (size_t)t * (BTOT * NGATES);
#pragma unroll
            for (int p = 0; p < 4; p++)
                xv2[bi][p] = *(const u64*)&src[p * HH];
        }

        // h_t (incl. peer half) must be visible
        asm volatile("barrier.cluster.wait.aligned;" ::: "memory");

        const float* hc = hbuf + cur * (CL_BT * HH);
        u64 acc2[BPT][4];
#pragma unroll
        for (int bi = 0; bi < BPT; bi++)
#pragma unroll
            for (int p = 0; p < 4; p++) acc2[bi][p] = 0ULL;

#pragma unroll 2
        for (int m = 0; m < HH; m += 4) {
            float4 hv[BPT];
#pragma unroll
            for (int bi = 0; bi < BPT; bi++)
                hv[bi] = *(const float4*)&hc[(wrp * BPT + bi) * HH + m];  // broadcast
#pragma unroll
            for (int mm = 0; mm < 4; mm++) {
                u64 w2[4];
#pragma unroll
                for (int p = 0; p < 4; p++)
                    w2[p] = *(const u64*)&Wt[(m + mm) * 256 + colbase + 64 * p];
#pragma unroll
                for (int bi = 0; bi < BPT; bi++) {
                    float h = (mm == 0) ? hv[bi].x : (mm == 1) ? hv[bi].y
                            : (mm == 2) ? hv[bi].z : hv[bi].w;
                    u64 h2; PACK_DUP(h2, h);
#pragma unroll
                    for (int p = 0; p < 4; p++)
                        FMA2(acc2[bi][p], h2, w2[p], acc2[bi][p]);
                }
            }
        }

        int nxt = cur ^ 1;
        float* hn = hbuf + nxt * (CL_BT * HH);
        uint32_t hn_peer = hbuf_peer + (uint32_t)(nxt * CL_BT * HH * 4);
#pragma unroll
        for (int bi = 0; bi < BPT; bi++) {
            u64 g2[4];
#pragma unroll
            for (int p = 0; p < 4; p++) ADD2(g2[p], acc2[bi][p], xv2[bi][p]);
            float giA, giB, gfA, gfB, ggA, ggB, goA, goB;
            UNPACK2(giA, giB, g2[0]);
            UNPACK2(gfA, gfB, g2[1]);
            UNPACK2(ggA, ggB, g2[2]);
            UNPACK2(goA, goB, g2[3]);
            float iA = sigf(giA), iB = sigf(giB);
            float fA = sigf(gfA), fB = sigf(gfB);
            float gA = tanh_f(ggA), gB = tanh_f(ggB);
            float oA = sigf(goA), oB = sigf(goB);
            float cA = fmaf(fA, cst[bi * 2], iA * gA);
            float cB = fmaf(fB, cst[bi * 2 + 1], iB * gB);
            cst[bi * 2] = cA;
            cst[bi * 2 + 1] = cB;
            float hA = oA * tanh_f(cA);
            float hB = oB * tanh_f(cB);
            hsum[bi * 2] += hA;
            hsum[bi * 2 + 1] += hB;
            int pos = (wrp * BPT + bi) * HH + (int)rank * 64 + colbase;
            u64 hp; PACK2(hp, hA, hB);
            *(u64*)&hn[pos] = hp;                                   // local
            asm volatile("st.shared::cluster.b64 [%0], %1;"        // peer
                         :: "r"(hn_peer + (uint32_t)(pos * 4)), "l"(hp) : "memory");
        }
        asm volatile("barrier.cluster.arrive.aligned;" ::: "memory");
        cur = nxt;
    }
    asm volatile("barrier.cluster.wait.aligned;" ::: "memory");  // balance phases

#pragma unroll
    for (int bi = 0; bi < BPT; bi++) {
        int b = b0 + wrp * BPT + bi;
        if (b < BTOT) {
            g_rep[b * HH + (int)rank * 64 + colbase]     = hsum[bi * 2];
            g_rep[b * HH + (int)rank * 64 + colbase + 1] = hsum[bi * 2 + 1];
        }
    }
}

// ============================================================================
// Kernel 3: per-graph mean over cycles, classifier, log_softmax. Tiny.
// ============================================================================
__global__ void cls_kernel(const float* __restrict__ W_cls, const float* __restrict__ b_cls,
                           float* __restrict__ out) {
    __shared__ float mean_s[HH];
    __shared__ float lg[NCLASS];
    int g = blockIdx.x, tid = threadIdx.x;
    float s = 0.f;
    for (int c = 0; c < NC; c++)
        s += g_rep[(g * NC + c) * HH + tid];
    mean_s[tid] = s * (1.0f / NC);
    __syncthreads();
    if (tid < NCLASS) {
        float d = b_cls[tid];
        for (int h = 0; h < HH; h++)
            d = fmaf(mean_s[h], W_cls[tid * HH + h], d);
        lg[tid] = d;
    }
    __syncthreads();
    if (tid == 0) {
        float mx = lg[0];
        for (int n = 1; n < NCLASS; n++) mx = fmaxf(mx, lg[n]);
        float sum = 0.f;
        for (int n = 0; n < NCLASS; n++) sum += expf(lg[n] - mx);
        float l = logf(sum);
        for (int n = 0; n < NCLASS; n++)
            out[g * NCLASS + n] = lg[n] - mx - l;
    }
}

extern "C" void kernel_launch(void* const* d_in, const int* in_sizes, int n_in,
                              void* d_out, int out_size) {
    (void)in_sizes; (void)n_in; (void)out_size;
    const float* x     = (const float*)d_in[0];  // cycle_reps [64,32,128,64]
    const float* W_ih  = (const float*)d_in[1];  // [512,64]
    const float* W_hh  = (const float*)d_in[2];  // [512,128]
    const float* b_ih  = (const float*)d_in[3];  // [512]
    const float* b_hh  = (const float*)d_in[4];  // [512]
    const float* W_cls = (const float*)d_in[5];  // [10,128]
    const float* b_cls = (const float*)d_in[6];  // [10]

    int smem1 = (DD * NGATES + 32 * DD) * (int)sizeof(float);          // 139264 B
    int smem2 = (HH * 256 + 2 * CL_BT * HH) * (int)sizeof(float);      // 159744 B
    cudaFuncSetAttribute(xg_kernel, cudaFuncAttributeMaxDynamicSharedMemorySize, smem1);
    cudaFuncSetAttribute(lstm_kernel, cudaFuncAttributeMaxDynamicSharedMemorySize, smem2);

    xg_kernel<<<148, 256, smem1>>>(x, W_ih, b_ih, b_hh);
    lstm_kernel<<<148, LSTM_THREADS, smem2>>>(W_hh);   // 74 clusters of 2
    cls_kernel<<<NG, HH>>>(W_cls, b_cls, (float*)d_out);
}

// round 5
// speedup vs baseline: 1.4905x; 1.1864x over previous
#include <cuda_runtime.h>
#include <cstdint>

#define NG 64
#define NC 32
#define LL 128
#define DD 64
#define HH 128
#define NCLASS 10
#define BTOT 2048          // G*C
#define NGATES 512         // 4*H

#define CL_BT 32           // batches per 2-CTA cluster (64 clusters exactly cover 2048)
#define LSTM_THREADS 256   // 8 warps; warp = 4 batches, lane = unit-pair
#define BPT 4              // batches per thread (per warp)

// Scratch (allocation-free rule: __device__ globals)
__device__ float g_xg[(size_t)BTOT * LL * NGATES];  // [b][t][gate]  (gate = torch i|f|g|o)
__device__ float g_rep[BTOT * HH];                  // sum_t h

typedef unsigned long long u64;

// packed f32x2 helpers (FFMA2 — PTX-only per SASS_QUICKREF)
#define FMA2(d, a, b, c) \
    asm("fma.rn.f32x2 %0, %1, %2, %3;" : "=l"(d) : "l"(a), "l"(b), "l"(c))
#define ADD2(d, a, b) \
    asm("add.rn.f32x2 %0, %1, %2;" : "=l"(d) : "l"(a), "l"(b))
#define PACK_DUP(d, f) \
    asm("mov.b64 %0, {%1, %1};" : "=l"(d) : "r"(__float_as_uint(f)))
#define PACK2(d, lo, hi) \
    asm("mov.b64 %0, {%1, %2};" : "=l"(d) : "r"(__float_as_uint(lo)), "r"(__float_as_uint(hi)))
#define UNPACK2(lo, hi, v) do { unsigned _ul, _uh;                         \
    asm("mov.b64 {%0, %1}, %2;" : "=r"(_ul), "=r"(_uh) : "l"(v));          \
    lo = __uint_as_float(_ul); hi = __uint_as_float(_uh); } while (0)

__device__ __forceinline__ float tanh_fast(float x) {
    float r;
    asm("tanh.approx.f32 %0, %1;" : "=f"(r) : "f"(x));
    return r;
}
__device__ __forceinline__ float sig_fast(float x) {
    return fmaf(0.5f, tanh_fast(0.5f * x), 0.5f);
}
__device__ __forceinline__ uint32_t to_tf32(float f) {
    uint32_t r;
    asm("cvt.rna.tf32.f32 %0, %1;" : "=r"(r) : "f"(f));
    return r;
}

// ============================================================================
// Kernel 1 (mma.sync tf32 — baseline PTX, works on sm_103 target):
//   g_xg[b][t][g] = sum_d x[b][t][d] * W_ih[g][d]   (bias folded into LSTM)
// 512 threads (16 warps) per CTA, persistent over 2048 batch-tiles.
// SMEM: Ws [512 gates][68] tf32 (resident), As [128 tokens][68] tf32 per tile.
// Warp (mg, ng): rows [32mg,32mg+32) x cols [128ng,128ng+128), processed in
// two 64-col halves (acc=64 regs). Frag loads conflict-free (68 mod 32 = 4).
// ============================================================================
#define XTHREADS 512
#define XPAD 68
#define XSM_W 0
#define XSM_A (NGATES * XPAD)
#define XSM_TOT ((NGATES + LL) * XPAD * 4)

__global__ void __launch_bounds__(XTHREADS, 1)
xg_mma_kernel(const float* __restrict__ x, const float* __restrict__ W_ih) {
    extern __shared__ float sm[];
    float* ws = sm + XSM_W;   // [512][68]
    float* as = sm + XSM_A;   // [128][68]
    int tid = threadIdx.x, wid = tid >> 5, lane = tid & 31;
    int t4 = lane >> 2, tm4 = lane & 3;
    int mg = wid >> 2, ng = wid & 3;

    // Stage W once: thread = one gate row (64 floats -> tf32)
    {
        const float4* src = (const float4*)(W_ih + (size_t)tid * DD);
        uint32_t* dst = (uint32_t*)&ws[tid * XPAD];
#pragma unroll
        for (int cc = 0; cc < 16; cc++) {
            float4 v = src[cc];
            uint4 u = make_uint4(to_tf32(v.x), to_tf32(v.y), to_tf32(v.z), to_tf32(v.w));
            *(uint4*)(dst + cc * 4) = u;
        }
    }

    for (int tile = blockIdx.x; tile < BTOT; tile += 148) {
        __syncthreads();  // WAR on As
        {   // stage x tile: 4 threads per token row, 16 floats each
            int row = tid >> 2, seg = tid & 3;
            const float4* src = (const float4*)(x + ((size_t)tile * LL + row) * DD) + seg * 4;
            uint32_t* dst = (uint32_t*)&as[row * XPAD + seg * 16];
#pragma unroll
            for (int cc = 0; cc < 4; cc++) {
                float4 v = src[cc];
                *(uint4*)(dst + cc * 4) =
                    make_uint4(to_tf32(v.x), to_tf32(v.y), to_tf32(v.z), to_tf32(v.w));
            }
        }
        __syncthreads();

#pragma unroll
        for (int half = 0; half < 2; half++) {
            int n0w = ng * 128 + half * 64;
            float acc[2][8][4];
#pragma unroll
            for (int mt = 0; mt < 2; mt++)
#pragma unroll
                for (int nc = 0; nc < 8; nc++)
#pragma unroll
                    for (int q = 0; q < 4; q++) acc[mt][nc][q] = 0.f;

#pragma unroll
            for (int k = 0; k < DD; k += 8) {
                uint32_t a[2][4];
#pragma unroll
                for (int mt = 0; mt < 2; mt++) {
                    int r0 = mg * 32 + mt * 16 + t4;
                    const uint32_t* ap = (const uint32_t*)as;
                    a[mt][0] = ap[r0 * XPAD + k + tm4];
                    a[mt][1] = ap[(r0 + 8) * XPAD + k + tm4];
                    a[mt][2] = ap[r0 * XPAD + k + tm4 + 4];
                    a[mt][3] = ap[(r0 + 8) * XPAD + k + tm4 + 4];
                }
#pragma unroll
                for (int nc = 0; nc < 8; nc++) {
                    int col = n0w + nc * 8 + t4;
                    const uint32_t* bp = (const uint32_t*)ws;
                    uint32_t b0 = bp[col * XPAD + k + tm4];
                    uint32_t b1 = bp[col * XPAD + k + tm4 + 4];
#pragma unroll
                    for (int mt = 0; mt < 2; mt++)
                        asm("mma.sync.aligned.m16n8k8.row.col.f32.tf32.tf32.f32 "
                            "{%0,%1,%2,%3}, {%4,%5,%6,%7}, {%8,%9}, {%0,%1,%2,%3};"
                            : "+f"(acc[mt][nc][0]), "+f"(acc[mt][nc][1]),
                              "+f"(acc[mt][nc][2]), "+f"(acc[mt][nc][3])
                            : "r"(a[mt][0]), "r"(a[mt][1]), "r"(a[mt][2]), "r"(a[mt][3]),
                              "r"(b0), "r"(b1));
                }
            }
            // epilogue: 32B-sector-aligned float2 stores
#pragma unroll
            for (int mt = 0; mt < 2; mt++) {
                int r = mg * 32 + mt * 16 + t4;
                float* dst = g_xg + ((size_t)tile * LL + r) * NGATES;
#pragma unroll
                for (int nc = 0; nc < 8; nc++) {
                    int c = n0w + nc * 8 + 2 * tm4;
                    *(float2*)(dst + c) = make_float2(acc[mt][nc][0], acc[mt][nc][1]);
                    *(float2*)(dst + 8 * NGATES + c) = make_float2(acc[mt][nc][2], acc[mt][nc][3]);
                }
            }
        }
    }
}

// ============================================================================
// Kernel 2: recurrent LSTM. 2-CTA cluster; rank r owns hidden units
// [r*64, r*64+64). 8 warps x 4 batches/thread. Lane l owns local unit pair
// (2l, 2l+1) for all 4 gates. FFMA2 GEMM; tanh.approx activations; bias
// folded into acc init.
// ============================================================================
__global__ void __launch_bounds__(LSTM_THREADS, 1) __cluster_dims__(2, 1, 1)
lstm_kernel(const float* __restrict__ W_hh,
            const float* __restrict__ b_ih, const float* __restrict__ b_hh) {
    extern __shared__ float sm[];
    float* Wt   = sm;               // [HH][256]: Wt[m*256 + c] = W_hh[row(c)][m]
    float* hbuf = sm + HH * 256;    // [2][CL_BT][HH]

    int tid = threadIdx.x;
    uint32_t rank;
    asm("mov.u32 %0, %%cluster_ctarank;" : "=r"(rank));
    int cid = blockIdx.x >> 1;
    int b0 = cid * CL_BT;
    int lane = tid & 31, wrp = tid >> 5;  // wrp in [0,8)

    for (int idx = tid; idx < 256 * HH; idx += LSTM_THREADS) {
        int c = idx >> 7, m = idx & 127;
        int row = ((c >> 6) * HH) + (int)rank * 64 + (c & 63);
        Wt[m * 256 + c] = W_hh[row * HH + m];
    }
    for (int idx = tid; idx < 2 * CL_BT * HH; idx += LSTM_THREADS)
        hbuf[idx] = 0.0f;   // h_0 = 0
    __syncthreads();

    uint32_t smem_local;
    asm("{ .reg .u64 t0; cvta.to.shared.u64 t0, %1; cvt.u32.u64 %0, t0; }"
        : "=r"(smem_local) : "l"(sm));
    uint32_t smem_peer;
    asm("mapa.shared::cluster.u32 %0, %1, %2;"
        : "=r"(smem_peer) : "r"(smem_local), "r"(rank ^ 1u));
    uint32_t hbuf_peer = smem_peer + (uint32_t)(HH * 256 * 4);

    const int colbase = 2 * lane;
    const float* xsrc[BPT];
#pragma unroll
    for (int bi = 0; bi < BPT; bi++) {
        int b = b0 + wrp * BPT + bi;
        xsrc[bi] = &g_xg[(size_t)b * (LL * NGATES) + (int)rank * 64 + colbase];
    }
    u64 bias2[4];
#pragma unroll
    for (int p = 0; p < 4; p++) {
        int g = p * HH + (int)rank * 64 + colbase;
        PACK2(bias2[p], b_ih[g] + b_hh[g], b_ih[g + 1] + b_hh[g + 1]);
    }

    float cst[2 * BPT], hsum[2 * BPT];
#pragma unroll
    for (int k = 0; k < 2 * BPT; k++) { cst[k] = 0.f; hsum[k] = 0.f; }

    asm volatile("barrier.cluster.arrive.aligned;" ::: "memory");

    int cur = 0;
#pragma unroll 1
    for (int t = 0; t < LL; t++) {
        u64 xv2[BPT][4];
#pragma unroll
        for (int bi = 0; bi < BPT; bi++) {
            const float* src = xsrc[bi] + (size_t)t * NGATES;
#pragma unroll
            for (int p = 0; p < 4; p++)
                xv2[bi][p] = *(const u64*)&src[p * HH];
        }

        asm volatile("barrier.cluster.wait.aligned;" ::: "memory");

        const float* hc = hbuf + cur * (CL_BT * HH);
        u64 acc2[BPT][4];
#pragma unroll
        for (int bi = 0; bi < BPT; bi++)
#pragma unroll
            for (int p = 0; p < 4; p++) acc2[bi][p] = bias2[p];

#pragma unroll 2
        for (int m = 0; m < HH; m += 4) {
            float4 hv[BPT];
#pragma unroll
            for (int bi = 0; bi < BPT; bi++)
                hv[bi] = *(const float4*)&hc[(wrp * BPT + bi) * HH + m];  // broadcast
#pragma unroll
            for (int mm = 0; mm < 4; mm++) {
                u64 w2[4];
#pragma unroll
                for (int p = 0; p < 4; p++)
                    w2[p] = *(const u64*)&Wt[(m + mm) * 256 + colbase + 64 * p];
#pragma unroll
                for (int bi = 0; bi < BPT; bi++) {
                    float h = (mm == 0) ? hv[bi].x : (mm == 1) ? hv[bi].y
                            : (mm == 2) ? hv[bi].z : hv[bi].w;
                    u64 h2; PACK_DUP(h2, h);
#pragma unroll
                    for (int p = 0; p < 4; p++)
                        FMA2(acc2[bi][p], h2, w2[p], acc2[bi][p]);
                }
            }
        }

        int nxt = cur ^ 1;
        float* hn = hbuf + nxt * (CL_BT * HH);
        uint32_t hn_peer = hbuf_peer + (uint32_t)(nxt * CL_BT * HH * 4);
#pragma unroll
        for (int bi = 0; bi < BPT; bi++) {
            u64 g2[4];
#pragma unroll
            for (int p = 0; p < 4; p++) ADD2(g2[p], acc2[bi][p], xv2[bi][p]);
            float giA, giB, gfA, gfB, ggA, ggB, goA, goB;
            UNPACK2(giA, giB, g2[0]);
            UNPACK2(gfA, gfB, g2[1]);
            UNPACK2(ggA, ggB, g2[2]);
            UNPACK2(goA, goB, g2[3]);
            float iA = sig_fast(giA), iB = sig_fast(giB);
            float fA = sig_fast(gfA), fB = sig_fast(gfB);
            float gA = tanh_fast(ggA), gB = tanh_fast(ggB);
            float oA = sig_fast(goA), oB = sig_fast(goB);
            float cA = fmaf(fA, cst[bi * 2], iA * gA);
            float cB = fmaf(fB, cst[bi * 2 + 1], iB * gB);
            cst[bi * 2] = cA;
            cst[bi * 2 + 1] = cB;
            float hA = oA * tanh_fast(cA);
            float hB = oB * tanh_fast(cB);
            hsum[bi * 2] += hA;
            hsum[bi * 2 + 1] += hB;
            int pos = (wrp * BPT + bi) * HH + (int)rank * 64 + colbase;
            u64 hp; PACK2(hp, hA, hB);
            *(u64*)&hn[pos] = hp;                                   // local
            asm volatile("st.shared::cluster.b64 [%0], %1;"        // peer
                         :: "r"(hn_peer + (uint32_t)(pos * 4)), "l"(hp) : "memory");
        }
        asm volatile("barrier.cluster.arrive.aligned;" ::: "memory");
        cur = nxt;
    }
    asm volatile("barrier.cluster.wait.aligned;" ::: "memory");  // balance phases

#pragma unroll
    for (int bi = 0; bi < BPT; bi++) {
        int b = b0 + wrp * BPT + bi;
        g_rep[b * HH + (int)rank * 64 + colbase]     = hsum[bi * 2];
        g_rep[b * HH + (int)rank * 64 + colbase + 1] = hsum[bi * 2 + 1];
    }
}

// ============================================================================
// Kernel 3: per-graph mean over cycles, classifier, log_softmax. Tiny.
// ============================================================================
__global__ void cls_kernel(const float* __restrict__ W_cls, const float* __restrict__ b_cls,
                           float* __restrict__ out) {
    __shared__ float mean_s[HH];
    __shared__ float lg[NCLASS];
    int g = blockIdx.x, tid = threadIdx.x;
    float s = 0.f;
    for (int c = 0; c < NC; c++)
        s += g_rep[(g * NC + c) * HH + tid];
    mean_s[tid] = s * (1.0f / NC);
    __syncthreads();
    if (tid < NCLASS) {
        float d = b_cls[tid];
        for (int h = 0; h < HH; h++)
            d = fmaf(mean_s[h], W_cls[tid * HH + h], d);
        lg[tid] = d;
    }
    __syncthreads();
    if (tid == 0) {
        float mx = lg[0];
        for (int n = 1; n < NCLASS; n++) mx = fmaxf(mx, lg[n]);
        float sum = 0.f;
        for (int n = 0; n < NCLASS; n++) sum += expf(lg[n] - mx);
        float l = logf(sum);
        for (int n = 0; n < NCLASS; n++)
            out[g * NCLASS + n] = lg[n] - mx - l;
    }
}

extern "C" void kernel_launch(void* const* d_in, const int* in_sizes, int n_in,
                              void* d_out, int out_size) {
    (void)in_sizes; (void)n_in; (void)out_size;
    const float* x     = (const float*)d_in[0];  // cycle_reps [64,32,128,64]
    const float* W_ih  = (const float*)d_in[1];  // [512,64]
    const float* W_hh  = (const float*)d_in[2];  // [512,128]
    const float* b_ih  = (const float*)d_in[3];  // [512]
    const float* b_hh  = (const float*)d_in[4];  // [512]
    const float* W_cls = (const float*)d_in[5];  // [10,128]
    const float* b_cls = (const float*)d_in[6];  // [10]

    int smem2 = (HH * 256 + 2 * CL_BT * HH) * (int)sizeof(float);      // 163840 B
    cudaFuncSetAttribute(xg_mma_kernel, cudaFuncAttributeMaxDynamicSharedMemorySize, XSM_TOT);
    cudaFuncSetAttribute(lstm_kernel, cudaFuncAttributeMaxDynamicSharedMemorySize, smem2);

    xg_mma_kernel<<<148, XTHREADS, XSM_TOT>>>(x, W_ih);
    lstm_kernel<<<128, LSTM_THREADS, smem2>>>(W_hh, b_ih, b_hh);   // 64 clusters of 2
    cls_kernel<<<NG, HH>>>(W_cls, b_cls, (float*)d_out);
}

// round 6
// speedup vs baseline: 2.0243x; 1.3581x over previous
#include <cuda_runtime.h>
#include <cstdint>

#define NG 64
#define NC 32
#define LL 128
#define DD 64
#define HH 128
#define NCLASS 10
#define BTOT 2048          // G*C
#define NGATES 512         // 4*H

// Scratch (allocation-free rule: __device__ globals)
__device__ float g_xg[(size_t)LL * BTOT * NGATES];  // [t][b][gate] (gate = torch i|f|g|o)
__device__ float g_rep[BTOT * HH];                  // sum_t h

typedef unsigned long long u64;

#define PACK2(d, lo, hi) \
    asm("mov.b64 %0, {%1, %2};" : "=l"(d) : "r"(__float_as_uint(lo)), "r"(__float_as_uint(hi)))

__device__ __forceinline__ float tanh_fast(float x) {
    float r;
    asm("tanh.approx.f32 %0, %1;" : "=f"(r) : "f"(x));
    return r;
}
__device__ __forceinline__ float sig_fast(float x) {
    return fmaf(0.5f, tanh_fast(0.5f * x), 0.5f);
}
__device__ __forceinline__ uint32_t to_tf32(float f) {
    uint32_t r;
    asm("cvt.rna.tf32.f32 %0, %1;" : "=r"(r) : "f"(f));
    return r;
}

#define MMA_TF32(acc, a0, a1, a2, a3, bb0, bb1) \
    asm("mma.sync.aligned.m16n8k8.row.col.f32.tf32.tf32.f32 " \
        "{%0,%1,%2,%3}, {%4,%5,%6,%7}, {%8,%9}, {%0,%1,%2,%3};" \
        : "+f"((acc)[0]), "+f"((acc)[1]), "+f"((acc)[2]), "+f"((acc)[3]) \
        : "r"(a0), "r"(a1), "r"(a2), "r"(a3), "r"(bb0), "r"(bb1))

// ============================================================================
// Kernel 1 (mma.sync tf32): g_xg[t][b][g] = sum_d x[b][t][d] * W_ih[g][d]
// (bias folded into LSTM). 512 threads/CTA, persistent over 2048 batch-tiles.
// Output layout is t-major ([t][b][512]) for the LSTM's streaming reads.
// ============================================================================
#define XTHREADS 512
#define XPAD 68
#define XSM_W 0
#define XSM_A (NGATES * XPAD)
#define XSM_TOT ((NGATES + LL) * XPAD * 4)

__global__ void __launch_bounds__(XTHREADS, 1)
xg_mma_kernel(const float* __restrict__ x, const float* __restrict__ W_ih) {
    extern __shared__ float sm[];
    float* ws = sm + XSM_W;   // [512][68]
    float* as = sm + XSM_A;   // [128][68]
    int tid = threadIdx.x, wid = tid >> 5, lane = tid & 31;
    int t4 = lane >> 2, tm4 = lane & 3;
    int mg = wid >> 2, ng = wid & 3;

    // Stage W once: thread = one gate row (64 floats -> tf32)
    {
        const float4* src = (const float4*)(W_ih + (size_t)tid * DD);
        uint32_t* dst = (uint32_t*)&ws[tid * XPAD];
#pragma unroll
        for (int cc = 0; cc < 16; cc++) {
            float4 v = src[cc];
            *(uint4*)(dst + cc * 4) =
                make_uint4(to_tf32(v.x), to_tf32(v.y), to_tf32(v.z), to_tf32(v.w));
        }
    }

    for (int tile = blockIdx.x; tile < BTOT; tile += 148) {
        __syncthreads();  // WAR on As
        {   // stage x tile: 4 threads per token row, 16 floats each
            int row = tid >> 2, seg = tid & 3;
            const float4* src = (const float4*)(x + ((size_t)tile * LL + row) * DD) + seg * 4;
            uint32_t* dst = (uint32_t*)&as[row * XPAD + seg * 16];
#pragma unroll
            for (int cc = 0; cc < 4; cc++) {
                float4 v = src[cc];
                *(uint4*)(dst + cc * 4) =
                    make_uint4(to_tf32(v.x), to_tf32(v.y), to_tf32(v.z), to_tf32(v.w));
            }
        }
        __syncthreads();

#pragma unroll
        for (int half = 0; half < 2; half++) {
            int n0w = ng * 128 + half * 64;
            float acc[2][8][4];
#pragma unroll
            for (int mt = 0; mt < 2; mt++)
#pragma unroll
                for (int nc = 0; nc < 8; nc++)
#pragma unroll
                    for (int q = 0; q < 4; q++) acc[mt][nc][q] = 0.f;

#pragma unroll
            for (int k = 0; k < DD; k += 8) {
                uint32_t a[2][4];
#pragma unroll
                for (int mt = 0; mt < 2; mt++) {
                    int r0 = mg * 32 + mt * 16 + t4;
                    const uint32_t* ap = (const uint32_t*)as;
                    a[mt][0] = ap[r0 * XPAD + k + tm4];
                    a[mt][1] = ap[(r0 + 8) * XPAD + k + tm4];
                    a[mt][2] = ap[r0 * XPAD + k + tm4 + 4];
                    a[mt][3] = ap[(r0 + 8) * XPAD + k + tm4 + 4];
                }
#pragma unroll
                for (int nc = 0; nc < 8; nc++) {
                    int col = n0w + nc * 8 + t4;
                    const uint32_t* bp = (const uint32_t*)ws;
                    uint32_t b0 = bp[col * XPAD + k + tm4];
                    uint32_t b1 = bp[col * XPAD + k + tm4 + 4];
#pragma unroll
                    for (int mt = 0; mt < 2; mt++)
                        MMA_TF32(acc[mt][nc], a[mt][0], a[mt][1], a[mt][2], a[mt][3], b0, b1);
                }
            }
            // epilogue: t-major layout, rows = t
#pragma unroll
            for (int mt = 0; mt < 2; mt++) {
                int r = mg * 32 + mt * 16 + t4;   // token t
                float* dst = g_xg + ((size_t)r * BTOT + tile) * NGATES;
                float* dst8 = dst + (size_t)8 * BTOT * NGATES;  // row r+8
#pragma unroll
                for (int nc = 0; nc < 8; nc++) {
                    int c = n0w + nc * 8 + 2 * tm4;
                    *(float2*)(dst + c)  = make_float2(acc[mt][nc][0], acc[mt][nc][1]);
                    *(float2*)(dst8 + c) = make_float2(acc[mt][nc][2], acc[mt][nc][3]);
                }
            }
        }
    }
}

// ============================================================================
// Kernel 2: recurrent LSTM via mma.sync tf32. 2-CTA cluster; rank r owns
// hidden units [r*64, r*64+64) = 256 gate-cols. 8 warps; warp w owns units
// 8w..8w+7 x 4 gates = 4 n8-tiles. M = 32 batches/cluster, K = 128.
// W stored as per-warp B-fragments in smem (conflict-free LDS.64); h double-
// buffered in padded smem [32][132]; h-halves exchanged via st.shared::cluster.
// Thread (t4,tm4) owns all 4 gates of units 8w+2tm4, +1 for 4 batch rows ->
// pointwise LSTM update fully register-resident. xg preacts prefetched from
// gmem before the cluster-barrier wait.
// ============================================================================
#define LSTM_THREADS 256
#define HPAD 132
#define WFRAG_FLOATS (8 * 16 * 4 * 64)            // 32768 floats = 128 KB
#define HB_OFF WFRAG_FLOATS
#define LSM_BYTES ((WFRAG_FLOATS + 2 * 32 * HPAD) * 4)   // 164864 B

__global__ void __launch_bounds__(LSTM_THREADS, 1) __cluster_dims__(2, 1, 1)
lstm_kernel(const float* __restrict__ W_hh,
            const float* __restrict__ b_ih, const float* __restrict__ b_hh) {
    extern __shared__ float sm[];
    float* wfrag = sm;                 // per-warp B fragments
    float* hbuf  = sm + HB_OFF;        // [2][32][HPAD]

    int tid = threadIdx.x, lane = tid & 31, w = tid >> 5;
    int t4 = lane >> 2, tm4 = lane & 3;
    uint32_t rank;
    asm("mov.u32 %0, %%cluster_ctarank;" : "=r"(rank));
    int cid = blockIdx.x >> 1;
    int b0 = cid * 32;
    int colbase = (int)rank * 64 + 8 * w + 2 * tm4;   // this thread's unit-pair col

    // Build W B-fragments (tf32): frag(n8k8) thread layout: n = t4, k = tm4/+4
#pragma unroll 4
    for (int kk = 0; kk < 16; kk++)
#pragma unroll
        for (int g = 0; g < 4; g++) {
            int row = g * HH + (int)rank * 64 + 8 * w + t4;   // W_hh gate row
            float v0 = W_hh[row * HH + kk * 8 + tm4];
            float v1 = W_hh[row * HH + kk * 8 + tm4 + 4];
            float2* d = (float2*)&wfrag[(((w * 16 + kk) * 4 + g) * 32 + lane) * 2];
            *d = make_float2(__uint_as_float(to_tf32(v0)), __uint_as_float(to_tf32(v1)));
        }
    for (int i = tid; i < 2 * 32 * HPAD; i += LSTM_THREADS)
        hbuf[i] = 0.0f;   // h_0 = 0, both buffers
    __syncthreads();

    uint32_t smem_local;
    asm("{ .reg .u64 t0; cvta.to.shared.u64 t0, %1; cvt.u32.u64 %0, t0; }"
        : "=r"(smem_local) : "l"(sm));
    uint32_t smem_peer;
    asm("mapa.shared::cluster.u32 %0, %1, %2;"
        : "=r"(smem_peer) : "r"(smem_local), "r"(rank ^ 1u));
    uint32_t hpeer = smem_peer + (uint32_t)(HB_OFF * 4);

    float2 bias2[4];
#pragma unroll
    for (int g = 0; g < 4; g++) {
        int c = g * HH + colbase;
        bias2[g] = make_float2(b_ih[c] + b_hh[c], b_ih[c + 1] + b_hh[c + 1]);
    }

    float cst[8], hsum[8];   // [mt*2+rs][unit]
#pragma unroll
    for (int k = 0; k < 8; k++) { cst[k] = 0.f; hsum[k] = 0.f; }

    asm volatile("barrier.cluster.arrive.aligned;" ::: "memory");

    int cur = 0;
#pragma unroll 1
    for (int t = 0; t < LL; t++) {
        // Prefetch xg preactivations for this step (gmem; consumed in epilogue)
        float2 xv[16];   // [(mt*2+rs)*4 + g]
        const float* xb = g_xg + (size_t)t * (BTOT * NGATES);
#pragma unroll
        for (int mt = 0; mt < 2; mt++)
#pragma unroll
            for (int rs = 0; rs < 2; rs++) {
                int b = b0 + mt * 16 + t4 + 8 * rs;
#pragma unroll
                for (int g = 0; g < 4; g++)
                    xv[(mt * 2 + rs) * 4 + g] =
                        *(const float2*)&xb[(size_t)b * NGATES + g * HH + colbase];
            }

        asm volatile("barrier.cluster.wait.aligned;" ::: "memory");

        const float* hc = hbuf + cur * (32 * HPAD);
        float acc[2][4][4];
#pragma unroll
        for (int mt = 0; mt < 2; mt++)
#pragma unroll
            for (int g = 0; g < 4; g++)
#pragma unroll
                for (int q = 0; q < 4; q++) acc[mt][g][q] = 0.f;

#pragma unroll
        for (int kk = 0; kk < 16; kk++) {
            uint32_t a[2][4];
#pragma unroll
            for (int mt = 0; mt < 2; mt++) {
                int r0 = (mt * 16 + t4) * HPAD + kk * 8 + tm4;
                a[mt][0] = __float_as_uint(hc[r0]);
                a[mt][1] = __float_as_uint(hc[r0 + 8 * HPAD]);
                a[mt][2] = __float_as_uint(hc[r0 + 4]);
                a[mt][3] = __float_as_uint(hc[r0 + 8 * HPAD + 4]);
            }
#pragma unroll
            for (int g = 0; g < 4; g++) {
                float2 bf = *(const float2*)&wfrag[(((w * 16 + kk) * 4 + g) * 32 + lane) * 2];
                uint32_t bb0 = __float_as_uint(bf.x), bb1 = __float_as_uint(bf.y);
                MMA_TF32(acc[0][g], a[0][0], a[0][1], a[0][2], a[0][3], bb0, bb1);
                MMA_TF32(acc[1][g], a[1][0], a[1][1], a[1][2], a[1][3], bb0, bb1);
            }
        }

        int nxt = cur ^ 1;
        float* hn = hbuf + nxt * (32 * HPAD);
        uint32_t hnp = hpeer + (uint32_t)(nxt * 32 * HPAD * 4);
#pragma unroll
        for (int mt = 0; mt < 2; mt++)
#pragma unroll
            for (int rs = 0; rs < 2; rs++) {
                int q = rs * 2;                    // C-frag reg pair for this row
                int ix = (mt * 2 + rs) * 4;
                float giA = acc[mt][0][q]     + xv[ix + 0].x + bias2[0].x;
                float giB = acc[mt][0][q + 1] + xv[ix + 0].y + bias2[0].y;
                float gfA = acc[mt][1][q]     + xv[ix + 1].x + bias2[1].x;
                float gfB = acc[mt][1][q + 1] + xv[ix + 1].y + bias2[1].y;
                float ggA = acc[mt][2][q]     + xv[ix + 2].x + bias2[2].x;
                float ggB = acc[mt][2][q + 1] + xv[ix + 2].y + bias2[2].y;
                float goA = acc[mt][3][q]     + xv[ix + 3].x + bias2[3].x;
                float goB = acc[mt][3][q + 1] + xv[ix + 3].y + bias2[3].y;
                float iA = sig_fast(giA), iB = sig_fast(giB);
                float fA = sig_fast(gfA), fB = sig_fast(gfB);
                float gA = tanh_fast(ggA), gB = tanh_fast(ggB);
                float oA = sig_fast(goA), oB = sig_fast(goB);
                int s = (mt * 2 + rs) * 2;
                float cA = fmaf(fA, cst[s],     iA * gA);
                float cB = fmaf(fB, cst[s + 1], iB * gB);
                cst[s] = cA; cst[s + 1] = cB;
                float hA = oA * tanh_fast(cA);
                float hB = oB * tanh_fast(cB);
                hsum[s] += hA; hsum[s + 1] += hB;
                // tf32-round h for next-step GEMM operand
                float hAr = __uint_as_float(to_tf32(hA));
                float hBr = __uint_as_float(to_tf32(hB));
                int pos = (mt * 16 + t4 + 8 * rs) * HPAD + colbase;
                *(float2*)&hn[pos] = make_float2(hAr, hBr);       // local half
                u64 hp; PACK2(hp, hAr, hBr);
                asm volatile("st.shared::cluster.b64 [%0], %1;"   // peer half
                             :: "r"(hnp + (uint32_t)(pos * 4)), "l"(hp) : "memory");
            }
        asm volatile("barrier.cluster.arrive.aligned;" ::: "memory");
        cur = nxt;
    }
    asm volatile("barrier.cluster.wait.aligned;" ::: "memory");  // balance phases

#pragma unroll
    for (int mt = 0; mt < 2; mt++)
#pragma unroll
        for (int rs = 0; rs < 2; rs++) {
            int b = b0 + mt * 16 + t4 + 8 * rs;
            int s = (mt * 2 + rs) * 2;
            *(float2*)&g_rep[b * HH + colbase] = make_float2(hsum[s], hsum[s + 1]);
        }
}

// ============================================================================
// Kernel 3: per-graph mean over cycles, classifier, log_softmax. Tiny.
// ============================================================================
__global__ void cls_kernel(const float* __restrict__ W_cls, const float* __restrict__ b_cls,
                           float* __restrict__ out) {
    __shared__ float mean_s[HH];
    __shared__ float lg[NCLASS];
    int g = blockIdx.x, tid = threadIdx.x;
    float s = 0.f;
    for (int c = 0; c < NC; c++)
        s += g_rep[(g * NC + c) * HH + tid];
    mean_s[tid] = s * (1.0f / NC);
    __syncthreads();
    if (tid < NCLASS) {
        float d = b_cls[tid];
        for (int h = 0; h < HH; h++)
            d = fmaf(mean_s[h], W_cls[tid * HH + h], d);
        lg[tid] = d;
    }
    __syncthreads();
    if (tid == 0) {
        float mx = lg[0];
        for (int n = 1; n < NCLASS; n++) mx = fmaxf(mx, lg[n]);
        float sum = 0.f;
        for (int n = 0; n < NCLASS; n++) sum += expf(lg[n] - mx);
        float l = logf(sum);
        for (int n = 0; n < NCLASS; n++)
            out[g * NCLASS + n] = lg[n] - mx - l;
    }
}

extern "C" void kernel_launch(void* const* d_in, const int* in_sizes, int n_in,
                              void* d_out, int out_size) {
    (void)in_sizes; (void)n_in; (void)out_size;
    const float* x     = (const float*)d_in[0];  // cycle_reps [64,32,128,64]
    const float* W_ih  = (const float*)d_in[1];  // [512,64]
    const float* W_hh  = (const float*)d_in[2];  // [512,128]
    const float* b_ih  = (const float*)d_in[3];  // [512]
    const float* b_hh  = (const float*)d_in[4];  // [512]
    const float* W_cls = (const float*)d_in[5];  // [10,128]
    const float* b_cls = (const float*)d_in[6];  // [10]

    cudaFuncSetAttribute(xg_mma_kernel, cudaFuncAttributeMaxDynamicSharedMemorySize, XSM_TOT);
    cudaFuncSetAttribute(lstm_kernel, cudaFuncAttributeMaxDynamicSharedMemorySize, LSM_BYTES);

    xg_mma_kernel<<<148, XTHREADS, XSM_TOT>>>(x, W_ih);
    lstm_kernel<<<128, LSTM_THREADS, LSM_BYTES>>>(W_hh, b_ih, b_hh);  // 64 clusters of 2
    cls_kernel<<<NG, HH>>>(W_cls, b_cls, (float*)d_out);
}

// round 7
// speedup vs baseline: 3.4265x; 1.6927x over previous
#include <cuda_runtime.h>
#include <cuda_bf16.h>
#include <cstdint>

#define NG 64
#define NC 32
#define LL 128
#define DD 64
#define HH 128
#define NCLASS 10
#define BTOT 2048          // G*C
#define NGATES 512         // 4*H

// Scratch (allocation-free rule: __device__ globals). xg stored bf16, b-major.
__device__ __nv_bfloat16 g_xg[(size_t)BTOT * LL * NGATES];  // [b][t][gate]
__device__ float g_rep[BTOT * HH];                          // sum_t h

typedef unsigned long long u64;

__device__ __forceinline__ float tanh_fast(float x) {
    float r;
    asm("tanh.approx.f32 %0, %1;" : "=f"(r) : "f"(x));
    return r;
}
__device__ __forceinline__ float sig_fast(float x) {
    return fmaf(0.5f, tanh_fast(0.5f * x), 0.5f);
}
__device__ __forceinline__ uint32_t to_tf32(float f) {
    uint32_t r;
    asm("cvt.rna.tf32.f32 %0, %1;" : "=r"(r) : "f"(f));
    return r;
}
__device__ __forceinline__ uint32_t pack_bf2(float lo, float hi) {
    __nv_bfloat162 v = __floats2bfloat162_rn(lo, hi);   // .x = lo
    return *(uint32_t*)&v;
}

#define MMA_TF32(acc, a0, a1, a2, a3, bb0, bb1) \
    asm("mma.sync.aligned.m16n8k8.row.col.f32.tf32.tf32.f32 " \
        "{%0,%1,%2,%3}, {%4,%5,%6,%7}, {%8,%9}, {%0,%1,%2,%3};" \
        : "+f"((acc)[0]), "+f"((acc)[1]), "+f"((acc)[2]), "+f"((acc)[3]) \
        : "r"(a0), "r"(a1), "r"(a2), "r"(a3), "r"(bb0), "r"(bb1))

#define MMA_BF16(acc, a0, a1, a2, a3, bb0, bb1) \
    asm("mma.sync.aligned.m16n8k16.row.col.f32.bf16.bf16.f32 " \
        "{%0,%1,%2,%3}, {%4,%5,%6,%7}, {%8,%9}, {%0,%1,%2,%3};" \
        : "+f"((acc)[0]), "+f"((acc)[1]), "+f"((acc)[2]), "+f"((acc)[3]) \
        : "r"(a0), "r"(a1), "r"(a2), "r"(a3), "r"(bb0), "r"(bb1))

// ============================================================================
// Kernel 1 (mma.sync tf32): g_xg[b][t][g] = sum_d x[b][t][d] * W_ih[g][d]
// (bias folded into LSTM). Round-5 structure (b-major, 164us measured);
// epilogue stores bf16x2 (halves DRAM writes).
// ============================================================================
#define XTHREADS 512
#define XPAD 68
#define XSM_W 0
#define XSM_A (NGATES * XPAD)
#define XSM_TOT ((NGATES + LL) * XPAD * 4)

__global__ void __launch_bounds__(XTHREADS, 1)
xg_mma_kernel(const float* __restrict__ x, const float* __restrict__ W_ih) {
    extern __shared__ float sm[];
    float* ws = sm + XSM_W;   // [512][68]
    float* as = sm + XSM_A;   // [128][68]
    int tid = threadIdx.x, wid = tid >> 5, lane = tid & 31;
    int t4 = lane >> 2, tm4 = lane & 3;
    int mg = wid >> 2, ng = wid & 3;

    // Stage W once: thread = one gate row (64 floats -> tf32)
    {
        const float4* src = (const float4*)(W_ih + (size_t)tid * DD);
        uint32_t* dst = (uint32_t*)&ws[tid * XPAD];
#pragma unroll
        for (int cc = 0; cc < 16; cc++) {
            float4 v = src[cc];
            *(uint4*)(dst + cc * 4) =
                make_uint4(to_tf32(v.x), to_tf32(v.y), to_tf32(v.z), to_tf32(v.w));
        }
    }

    for (int tile = blockIdx.x; tile < BTOT; tile += 148) {
        __syncthreads();  // WAR on As
        {   // stage x tile: 4 threads per token row, 16 floats each
            int row = tid >> 2, seg = tid & 3;
            const float4* src = (const float4*)(x + ((size_t)tile * LL + row) * DD) + seg * 4;
            uint32_t* dst = (uint32_t*)&as[row * XPAD + seg * 16];
#pragma unroll
            for (int cc = 0; cc < 4; cc++) {
                float4 v = src[cc];
                *(uint4*)(dst + cc * 4) =
                    make_uint4(to_tf32(v.x), to_tf32(v.y), to_tf32(v.z), to_tf32(v.w));
            }
        }
        __syncthreads();

#pragma unroll
        for (int half = 0; half < 2; half++) {
            int n0w = ng * 128 + half * 64;
            float acc[2][8][4];
#pragma unroll
            for (int mt = 0; mt < 2; mt++)
#pragma unroll
                for (int nc = 0; nc < 8; nc++)
#pragma unroll
                    for (int q = 0; q < 4; q++) acc[mt][nc][q] = 0.f;

#pragma unroll
            for (int k = 0; k < DD; k += 8) {
                uint32_t a[2][4];
#pragma unroll
                for (int mt = 0; mt < 2; mt++) {
                    int r0 = mg * 32 + mt * 16 + t4;
                    const uint32_t* ap = (const uint32_t*)as;
                    a[mt][0] = ap[r0 * XPAD + k + tm4];
                    a[mt][1] = ap[(r0 + 8) * XPAD + k + tm4];
                    a[mt][2] = ap[r0 * XPAD + k + tm4 + 4];
                    a[mt][3] = ap[(r0 + 8) * XPAD + k + tm4 + 4];
                }
#pragma unroll
                for (int nc = 0; nc < 8; nc++) {
                    int col = n0w + nc * 8 + t4;
                    const uint32_t* bp = (const uint32_t*)ws;
                    uint32_t b0 = bp[col * XPAD + k + tm4];
                    uint32_t b1 = bp[col * XPAD + k + tm4 + 4];
#pragma unroll
                    for (int mt = 0; mt < 2; mt++)
                        MMA_TF32(acc[mt][nc], a[mt][0], a[mt][1], a[mt][2], a[mt][3], b0, b1);
                }
            }
            // epilogue: bf16x2 stores, b-major
#pragma unroll
            for (int mt = 0; mt < 2; mt++) {
                int r = mg * 32 + mt * 16 + t4;
                __nv_bfloat16* dst = g_xg + ((size_t)tile * LL + r) * NGATES;
                __nv_bfloat16* dst8 = dst + (size_t)8 * NGATES;
#pragma unroll
                for (int nc = 0; nc < 8; nc++) {
                    int c = n0w + nc * 8 + 2 * tm4;
                    *(uint32_t*)(dst + c)  = pack_bf2(acc[mt][nc][0], acc[mt][nc][1]);
                    *(uint32_t*)(dst8 + c) = pack_bf2(acc[mt][nc][2], acc[mt][nc][3]);
                }
            }
        }
    }
}

// ============================================================================
// Kernel 2: recurrent LSTM via mma.sync m16n8k16 bf16. 2-CTA cluster; rank r
// owns hidden units [r*64, r*64+64). 8 warps; warp w = units 8w..8w+7 x 4
// gates. K = 128 -> 8 kk steps of 16.
// SMEM (uint4 arrays, 16B/lane stride => conflict-free LDS.128):
//   whfq: W_hh bf16 B-fragments [w][kk][quad(2)][lane]      (64 KB, resident)
//   hfq : h bf16 A-fragments [buf(2)][kk(8)][mt(2)][lane]   (16 KB, dbl-buf)
// Producer lane == consumer lane for the A-frag (layout identity), so h is
// written directly in fragment form: 2 STS.64 local + 2 remote b64 / thread.
// xg preacts (bf16) prefetched from gmem before the cluster-barrier wait.
// ============================================================================
#define LSTM_THREADS 256
#define WHFQ_QUADS (8 * 8 * 2 * 32)          // 4096 uint4 = 64 KB
#define HFQ_OFF WHFQ_QUADS                   // quad index offset
#define LSM_BYTES ((WHFQ_QUADS + 2 * 8 * 2 * 32) * 16)   // 81920 B

__global__ void __launch_bounds__(LSTM_THREADS, 1) __cluster_dims__(2, 1, 1)
lstm_kernel(const float* __restrict__ W_hh,
            const float* __restrict__ b_ih, const float* __restrict__ b_hh) {
    extern __shared__ uint4 smq[];
    uint4* whfq = smq;             // [((w*8+kk)*2+q)*32 + lane]
    uint4* hfq  = smq + HFQ_OFF;   // [(((buf*8)+kk)*2+mt)*32 + lane]

    int tid = threadIdx.x, lane = tid & 31, w = tid >> 5;
    int t4 = lane >> 2, tm4 = lane & 3;
    uint32_t rank;
    asm("mov.u32 %0, %%cluster_ctarank;" : "=r"(rank));
    int cid = blockIdx.x >> 1;
    int b0 = cid * 32;
    int colbase = (int)rank * 64 + 8 * w + 2 * tm4;   // unit-pair col [0,128)

    // Build W_hh bf16 B-fragments. quad0 = (g0b0,g0b1,g1b0,g1b1), quad1 = g2,g3.
#pragma unroll 2
    for (int kk = 0; kk < 8; kk++) {
        uint32_t bb[4][2];
#pragma unroll
        for (int g = 0; g < 4; g++) {
            int row = g * HH + (int)rank * 64 + 8 * w + t4;
            float2 lo2 = *(const float2*)&W_hh[row * HH + kk * 16 + 2 * tm4];
            float2 hi2 = *(const float2*)&W_hh[row * HH + kk * 16 + 2 * tm4 + 8];
            bb[g][0] = pack_bf2(lo2.x, lo2.y);
            bb[g][1] = pack_bf2(hi2.x, hi2.y);
        }
        whfq[((w * 8 + kk) * 2 + 0) * 32 + lane] =
            make_uint4(bb[0][0], bb[0][1], bb[1][0], bb[1][1]);
        whfq[((w * 8 + kk) * 2 + 1) * 32 + lane] =
            make_uint4(bb[2][0], bb[2][1], bb[3][0], bb[3][1]);
    }
    // zero h fragments (both buffers)
    for (int i = tid; i < 2 * 8 * 2 * 32; i += LSTM_THREADS)
        hfq[i] = make_uint4(0, 0, 0, 0);
    __syncthreads();

    uint32_t smem_local;
    asm("{ .reg .u64 t0; cvta.to.shared.u64 t0, %1; cvt.u32.u64 %0, t0; }"
        : "=r"(smem_local) : "l"((void*)smq));
    uint32_t smem_peer;
    asm("mapa.shared::cluster.u32 %0, %1, %2;"
        : "=r"(smem_peer) : "r"(smem_local), "r"(rank ^ 1u));
    uint32_t hfq_peer = smem_peer + (uint32_t)(HFQ_OFF * 16);

    // Producer frag coordinates: kk' and word offset are warp constants.
    const int kkp = (int)rank * 4 + (w >> 1);   // this thread's A-frag kk
    const int wordoff = 8 * (w & 1);            // byte offset of (rs0,rs1) word pair

    float2 bias2[4];
#pragma unroll
    for (int g = 0; g < 4; g++) {
        int c = g * HH + colbase;
        bias2[g] = make_float2(b_ih[c] + b_hh[c], b_ih[c + 1] + b_hh[c + 1]);
    }

    float cst[8], hsum[8];   // [(mt*2+rs)*2 + unit]
#pragma unroll
    for (int k = 0; k < 8; k++) { cst[k] = 0.f; hsum[k] = 0.f; }

    asm volatile("barrier.cluster.arrive.aligned;" ::: "memory");

    int cur = 0;
#pragma unroll 1
    for (int t = 0; t < LL; t++) {
        // Prefetch xg preacts (bf16 gmem; consumed in epilogue)
        uint32_t xr[16];   // [(mt*2+rs)*4 + g]
#pragma unroll
        for (int mt = 0; mt < 2; mt++)
#pragma unroll
            for (int rs = 0; rs < 2; rs++) {
                int b = b0 + mt * 16 + t4 + 8 * rs;
                const __nv_bfloat16* src = g_xg + ((size_t)b * LL + t) * NGATES;
#pragma unroll
                for (int g = 0; g < 4; g++)
                    xr[(mt * 2 + rs) * 4 + g] =
                        *(const uint32_t*)(src + g * HH + colbase);
            }

        asm volatile("barrier.cluster.wait.aligned;" ::: "memory");

        float acc[2][4][4];
#pragma unroll
        for (int mt = 0; mt < 2; mt++)
#pragma unroll
            for (int g = 0; g < 4; g++)
#pragma unroll
                for (int q = 0; q < 4; q++) acc[mt][g][q] = 0.f;

        const uint4* hb = hfq + (cur * 8) * 2 * 32;
#pragma unroll
        for (int kk = 0; kk < 8; kk++) {
            uint4 aq0 = hb[(kk * 2 + 0) * 32 + lane];   // mt=0: a0,a1,a2,a3
            uint4 aq1 = hb[(kk * 2 + 1) * 32 + lane];   // mt=1
            uint4 wq0 = whfq[((w * 8 + kk) * 2 + 0) * 32 + lane];
            uint4 wq1 = whfq[((w * 8 + kk) * 2 + 1) * 32 + lane];
            MMA_BF16(acc[0][0], aq0.x, aq0.y, aq0.z, aq0.w, wq0.x, wq0.y);
            MMA_BF16(acc[0][1], aq0.x, aq0.y, aq0.z, aq0.w, wq0.z, wq0.w);
            MMA_BF16(acc[0][2], aq0.x, aq0.y, aq0.z, aq0.w, wq1.x, wq1.y);
            MMA_BF16(acc[0][3], aq0.x, aq0.y, aq0.z, aq0.w, wq1.z, wq1.w);
            MMA_BF16(acc[1][0], aq1.x, aq1.y, aq1.z, aq1.w, wq0.x, wq0.y);
            MMA_BF16(acc[1][1], aq1.x, aq1.y, aq1.z, aq1.w, wq0.z, wq0.w);
            MMA_BF16(acc[1][2], aq1.x, aq1.y, aq1.z, aq1.w, wq1.x, wq1.y);
            MMA_BF16(acc[1][3], aq1.x, aq1.y, aq1.z, aq1.w, wq1.z, wq1.w);
        }

        int nxt = cur ^ 1;
#pragma unroll
        for (int mt = 0; mt < 2; mt++) {
            uint32_t hv[2];   // packed bf16x2 per rs
#pragma unroll
            for (int rs = 0; rs < 2; rs++) {
                int q = rs * 2;
                int ix = (mt * 2 + rs) * 4;
                float2 x0 = __bfloat1622float2(*(__nv_bfloat162*)&xr[ix + 0]);
                float2 x1 = __bfloat1622float2(*(__nv_bfloat162*)&xr[ix + 1]);
                float2 x2 = __bfloat1622float2(*(__nv_bfloat162*)&xr[ix + 2]);
                float2 x3 = __bfloat1622float2(*(__nv_bfloat162*)&xr[ix + 3]);
                float iA = sig_fast(acc[mt][0][q]     + x0.x + bias2[0].x);
                float iB = sig_fast(acc[mt][0][q + 1] + x0.y + bias2[0].y);
                float fA = sig_fast(acc[mt][1][q]     + x1.x + bias2[1].x);
                float fB = sig_fast(acc[mt][1][q + 1] + x1.y + bias2[1].y);
                float gA = tanh_fast(acc[mt][2][q]     + x2.x + bias2[2].x);
                float gB = tanh_fast(acc[mt][2][q + 1] + x2.y + bias2[2].y);
                float oA = sig_fast(acc[mt][3][q]     + x3.x + bias2[3].x);
                float oB = sig_fast(acc[mt][3][q + 1] + x3.y + bias2[3].y);
                int s = (mt * 2 + rs) * 2;
                float cA = fmaf(fA, cst[s],     iA * gA);
                float cB = fmaf(fB, cst[s + 1], iB * gB);
                cst[s] = cA; cst[s + 1] = cB;
                float hA = oA * tanh_fast(cA);
                float hB = oB * tanh_fast(cB);
                hsum[s] += hA; hsum[s + 1] += hB;
                hv[rs] = pack_bf2(hA, hB);
            }
            // A-frag store: quad = ((nxt*8+kkp)*2+mt), words (2(w&1), +1) = (rs0, rs1)
            uint32_t boff = (uint32_t)((HFQ_OFF + ((nxt * 8 + kkp) * 2 + mt) * 32 + lane) * 16
                                       + wordoff);
            u64 pp;
            asm("mov.b64 %0, {%1, %2};" : "=l"(pp) : "r"(hv[0]), "r"(hv[1]));
            asm volatile("st.shared.b64 [%0], %1;"
                         :: "r"(smem_local + boff), "l"(pp) : "memory");
            asm volatile("st.shared::cluster.b64 [%0], %1;"
                         :: "r"(smem_peer + boff), "l"(pp) : "memory");
        }
        asm volatile("barrier.cluster.arrive.aligned;" ::: "memory");
        cur = nxt;
    }
    asm volatile("barrier.cluster.wait.aligned;" ::: "memory");  // balance phases

#pragma unroll
    for (int mt = 0; mt < 2; mt++)
#pragma unroll
        for (int rs = 0; rs < 2; rs++) {
            int b = b0 + mt * 16 + t4 + 8 * rs;
            int s = (mt * 2 + rs) * 2;
            *(float2*)&g_rep[b * HH + colbase] = make_float2(hsum[s], hsum[s + 1]);
        }
}

// ============================================================================
// Kernel 3: per-graph mean over cycles, classifier, log_softmax. Tiny.
// ============================================================================
__global__ void cls_kernel(const float* __restrict__ W_cls, const float* __restrict__ b_cls,
                           float* __restrict__ out) {
    __shared__ float mean_s[HH];
    __shared__ float lg[NCLASS];
    int g = blockIdx.x, tid = threadIdx.x;
    float s = 0.f;
    for (int c = 0; c < NC; c++)
        s += g_rep[(g * NC + c) * HH + tid];
    mean_s[tid] = s * (1.0f / NC);
    __syncthreads();
    if (tid < NCLASS) {
        float d = b_cls[tid];
        for (int h = 0; h < HH; h++)
            d = fmaf(mean_s[h], W_cls[tid * HH + h], d);
        lg[tid] = d;
    }
    __syncthreads();
    if (tid == 0) {
        float mx = lg[0];
        for (int n = 1; n < NCLASS; n++) mx = fmaxf(mx, lg[n]);
        float sum = 0.f;
        for (int n = 0; n < NCLASS; n++) sum += expf(lg[n] - mx);
        float l = logf(sum);
        for (int n = 0; n < NCLASS; n++)
            out[g * NCLASS + n] = lg[n] - mx - l;
    }
}

extern "C" void kernel_launch(void* const* d_in, const int* in_sizes, int n_in,
                              void* d_out, int out_size) {
    (void)in_sizes; (void)n_in; (void)out_size;
    const float* x     = (const float*)d_in[0];  // cycle_reps [64,32,128,64]
    const float* W_ih  = (const float*)d_in[1];  // [512,64]
    const float* W_hh  = (const float*)d_in[2];  // [512,128]
    const float* b_ih  = (const float*)d_in[3];  // [512]
    const float* b_hh  = (const float*)d_in[4];  // [512]
    const float* W_cls = (const float*)d_in[5];  // [10,128]
    const float* b_cls = (const float*)d_in[6];  // [10]

    cudaFuncSetAttribute(xg_mma_kernel, cudaFuncAttributeMaxDynamicSharedMemorySize, XSM_TOT);
    cudaFuncSetAttribute(lstm_kernel, cudaFuncAttributeMaxDynamicSharedMemorySize, LSM_BYTES);

    xg_mma_kernel<<<148, XTHREADS, XSM_TOT>>>(x, W_ih);
    lstm_kernel<<<128, LSTM_THREADS, LSM_BYTES>>>(W_hh, b_ih, b_hh);  // 64 clusters of 2
    cls_kernel<<<NG, HH>>>(W_cls, b_cls, (float*)d_out);
}

// round 8
// speedup vs baseline: 5.0340x; 1.4692x over previous
#include <cuda_runtime.h>
#include <cuda_bf16.h>
#include <cstdint>

#define NG 64
#define NC 32
#define LL 128
#define DD 64
#define HH 128
#define NCLASS 10
#define BTOT 2048          // G*C
#define NGATES 512         // 4*H

// Scratch (allocation-free rule: __device__ globals). xg stored bf16, b-major.
__device__ __nv_bfloat16 g_xg[(size_t)BTOT * LL * NGATES];  // [b][t][gate]
__device__ float g_rep[BTOT * HH];                          // sum_t h

typedef unsigned long long u64;

__device__ __forceinline__ float tanh_fast(float x) {
    float r;
    asm("tanh.approx.f32 %0, %1;" : "=f"(r) : "f"(x));
    return r;
}
__device__ __forceinline__ float sig_fast(float x) {
    return fmaf(0.5f, tanh_fast(0.5f * x), 0.5f);
}
__device__ __forceinline__ uint32_t to_tf32(float f) {
    uint32_t r;
    asm("cvt.rna.tf32.f32 %0, %1;" : "=r"(r) : "f"(f));
    return r;
}
__device__ __forceinline__ uint32_t pack_bf2(float lo, float hi) {
    __nv_bfloat162 v = __floats2bfloat162_rn(lo, hi);   // .x = lo
    return *(uint32_t*)&v;
}

#define MMA_TF32(acc, a0, a1, a2, a3, bb0, bb1) \
    asm("mma.sync.aligned.m16n8k8.row.col.f32.tf32.tf32.f32 " \
        "{%0,%1,%2,%3}, {%4,%5,%6,%7}, {%8,%9}, {%0,%1,%2,%3};" \
        : "+f"((acc)[0]), "+f"((acc)[1]), "+f"((acc)[2]), "+f"((acc)[3]) \
        : "r"(a0), "r"(a1), "r"(a2), "r"(a3), "r"(bb0), "r"(bb1))

#define MMA_BF16(acc, a0, a1, a2, a3, bb0, bb1) \
    asm("mma.sync.aligned.m16n8k16.row.col.f32.bf16.bf16.f32 " \
        "{%0,%1,%2,%3}, {%4,%5,%6,%7}, {%8,%9}, {%0,%1,%2,%3};" \
        : "+f"((acc)[0]), "+f"((acc)[1]), "+f"((acc)[2]), "+f"((acc)[3]) \
        : "r"(a0), "r"(a1), "r"(a2), "r"(a3), "r"(bb0), "r"(bb1))

// ============================================================================
// Kernel 1 (mma.sync tf32): g_xg[b][t][g] = sum_d x[b][t][d] * W_ih[g][d]
// (bias folded into LSTM). Unchanged from round 7 (164us measured).
// ============================================================================
#define XTHREADS 512
#define XPAD 68
#define XSM_W 0
#define XSM_A (NGATES * XPAD)
#define XSM_TOT ((NGATES + LL) * XPAD * 4)

__global__ void __launch_bounds__(XTHREADS, 1)
xg_mma_kernel(const float* __restrict__ x, const float* __restrict__ W_ih) {
    extern __shared__ float sm[];
    float* ws = sm + XSM_W;   // [512][68]
    float* as = sm + XSM_A;   // [128][68]
    int tid = threadIdx.x, wid = tid >> 5, lane = tid & 31;
    int t4 = lane >> 2, tm4 = lane & 3;
    int mg = wid >> 2, ng = wid & 3;

    // Stage W once: thread = one gate row (64 floats -> tf32)
    {
        const float4* src = (const float4*)(W_ih + (size_t)tid * DD);
        uint32_t* dst = (uint32_t*)&ws[tid * XPAD];
#pragma unroll
        for (int cc = 0; cc < 16; cc++) {
            float4 v = src[cc];
            *(uint4*)(dst + cc * 4) =
                make_uint4(to_tf32(v.x), to_tf32(v.y), to_tf32(v.z), to_tf32(v.w));
        }
    }

    for (int tile = blockIdx.x; tile < BTOT; tile += 148) {
        __syncthreads();  // WAR on As
        {   // stage x tile: 4 threads per token row, 16 floats each
            int row = tid >> 2, seg = tid & 3;
            const float4* src = (const float4*)(x + ((size_t)tile * LL + row) * DD) + seg * 4;
            uint32_t* dst = (uint32_t*)&as[row * XPAD + seg * 16];
#pragma unroll
            for (int cc = 0; cc < 4; cc++) {
                float4 v = src[cc];
                *(uint4*)(dst + cc * 4) =
                    make_uint4(to_tf32(v.x), to_tf32(v.y), to_tf32(v.z), to_tf32(v.w));
            }
        }
        __syncthreads();

#pragma unroll
        for (int half = 0; half < 2; half++) {
            int n0w = ng * 128 + half * 64;
            float acc[2][8][4];
#pragma unroll
            for (int mt = 0; mt < 2; mt++)
#pragma unroll
                for (int nc = 0; nc < 8; nc++)
#pragma unroll
                    for (int q = 0; q < 4; q++) acc[mt][nc][q] = 0.f;

#pragma unroll
            for (int k = 0; k < DD; k += 8) {
                uint32_t a[2][4];
#pragma unroll
                for (int mt = 0; mt < 2; mt++) {
                    int r0 = mg * 32 + mt * 16 + t4;
                    const uint32_t* ap = (const uint32_t*)as;
                    a[mt][0] = ap[r0 * XPAD + k + tm4];
                    a[mt][1] = ap[(r0 + 8) * XPAD + k + tm4];
                    a[mt][2] = ap[r0 * XPAD + k + tm4 + 4];
                    a[mt][3] = ap[(r0 + 8) * XPAD + k + tm4 + 4];
                }
#pragma unroll
                for (int nc = 0; nc < 8; nc++) {
                    int col = n0w + nc * 8 + t4;
                    const uint32_t* bp = (const uint32_t*)ws;
                    uint32_t b0 = bp[col * XPAD + k + tm4];
                    uint32_t b1 = bp[col * XPAD + k + tm4 + 4];
#pragma unroll
                    for (int mt = 0; mt < 2; mt++)
                        MMA_TF32(acc[mt][nc], a[mt][0], a[mt][1], a[mt][2], a[mt][3], b0, b1);
                }
            }
            // epilogue: bf16x2 stores, b-major
#pragma unroll
            for (int mt = 0; mt < 2; mt++) {
                int r = mg * 32 + mt * 16 + t4;
                __nv_bfloat16* dst = g_xg + ((size_t)tile * LL + r) * NGATES;
                __nv_bfloat16* dst8 = dst + (size_t)8 * NGATES;
#pragma unroll
                for (int nc = 0; nc < 8; nc++) {
                    int c = n0w + nc * 8 + 2 * tm4;
                    *(uint32_t*)(dst + c)  = pack_bf2(acc[mt][nc][0], acc[mt][nc][1]);
                    *(uint32_t*)(dst8 + c) = pack_bf2(acc[mt][nc][2], acc[mt][nc][3]);
                }
            }
        }
    }
}

// ============================================================================
// Kernel 2: recurrent LSTM, single-CTA (no cluster), mma.sync m16n8k16 bf16.
// 128 CTAs x 512 threads; CTA owns 16 batches, ALL 512 gate-cols.
// Warp w (0..15) owns hidden units 8w..8w+7 x 4 gates = 4 n8-tiles.
// W_hh B-fragments live in REGISTERS (64 regs/thread, loaded once) -> zero
// per-step W smem traffic. h A-fragments in smem [2 buf][8 kk][32 lanes]
// (8 KB): producer-lane == consumer-lane identity means each thread stores
// its h unit-pair with ONE STS.64 directly in fragment layout.
// Per-step sync = one __syncthreads (vs ~490-cyc cluster barrier).
// ============================================================================
#define LSTM_THREADS 512

__global__ void __launch_bounds__(LSTM_THREADS, 1)
lstm_kernel(const float* __restrict__ W_hh,
            const float* __restrict__ b_ih, const float* __restrict__ b_hh) {
    __shared__ uint4 hfq[2][8][32];   // [buf][kk][lane] = {a0,a1,a2,a3}

    int tid = threadIdx.x, lane = tid & 31, w = tid >> 5;   // w in [0,16)
    int t4 = lane >> 2, tm4 = lane & 3;
    int b0 = blockIdx.x * 16;
    int colbase = 8 * w + 2 * tm4;    // unit pair (colbase, colbase+1) in [0,128)

    // W_hh bf16 B-fragments -> registers (one-time). Frag col n = t4.
    uint32_t wb0[8][4], wb1[8][4];
#pragma unroll
    for (int kk = 0; kk < 8; kk++)
#pragma unroll
        for (int g = 0; g < 4; g++) {
            int row = g * HH + 8 * w + t4;
            float2 lo2 = *(const float2*)&W_hh[row * HH + kk * 16 + 2 * tm4];
            float2 hi2 = *(const float2*)&W_hh[row * HH + kk * 16 + 2 * tm4 + 8];
            wb0[kk][g] = pack_bf2(lo2.x, lo2.y);
            wb1[kk][g] = pack_bf2(hi2.x, hi2.y);
        }

    // zero h fragments (both buffers): 512 entries, 512 threads
    ((uint4*)hfq)[tid] = make_uint4(0, 0, 0, 0);

    // Producer store coordinates (warp constants)
    const int kkp = w >> 1;
    const int wordoff = 8 * (w & 1);   // bytes: w even -> a0,a1; w odd -> a2,a3

    float2 bias2[4];
#pragma unroll
    for (int g = 0; g < 4; g++) {
        int c = g * HH + colbase;
        bias2[g] = make_float2(b_ih[c] + b_hh[c], b_ih[c + 1] + b_hh[c + 1]);
    }

    float cst[4], hsum[4];   // [rs*2 + unit]
#pragma unroll
    for (int k = 0; k < 4; k++) { cst[k] = 0.f; hsum[k] = 0.f; }

    __syncthreads();

    int cur = 0;
#pragma unroll 1
    for (int t = 0; t < LL; t++) {
        // Prefetch xg preacts (bf16 gmem; consumed in epilogue)
        uint32_t xr[8];   // [rs*4 + g]
#pragma unroll
        for (int rs = 0; rs < 2; rs++) {
            int b = b0 + t4 + 8 * rs;
            const __nv_bfloat16* src = g_xg + ((size_t)b * LL + t) * NGATES;
#pragma unroll
            for (int g = 0; g < 4; g++)
                xr[rs * 4 + g] = *(const uint32_t*)(src + g * HH + colbase);
        }

        __syncthreads();   // h[cur] fragment stores (prev step) visible

        float acc[4][4];
#pragma unroll
        for (int g = 0; g < 4; g++)
#pragma unroll
            for (int q = 0; q < 4; q++) acc[g][q] = 0.f;

#pragma unroll
        for (int kk = 0; kk < 8; kk++) {
            uint4 aq = hfq[cur][kk][lane];
            MMA_BF16(acc[0], aq.x, aq.y, aq.z, aq.w, wb0[kk][0], wb1[kk][0]);
            MMA_BF16(acc[1], aq.x, aq.y, aq.z, aq.w, wb0[kk][1], wb1[kk][1]);
            MMA_BF16(acc[2], aq.x, aq.y, aq.z, aq.w, wb0[kk][2], wb1[kk][2]);
            MMA_BF16(acc[3], aq.x, aq.y, aq.z, aq.w, wb0[kk][3], wb1[kk][3]);
        }

        int nxt = cur ^ 1;
        uint32_t hv[2];
#pragma unroll
        for (int rs = 0; rs < 2; rs++) {
            int q = rs * 2;   // C-frag: q0,q1 = row t4; q2,q3 = row t4+8
            float2 x0 = __bfloat1622float2(*(__nv_bfloat162*)&xr[rs * 4 + 0]);
            float2 x1 = __bfloat1622float2(*(__nv_bfloat162*)&xr[rs * 4 + 1]);
            float2 x2 = __bfloat1622float2(*(__nv_bfloat162*)&xr[rs * 4 + 2]);
            float2 x3 = __bfloat1622float2(*(__nv_bfloat162*)&xr[rs * 4 + 3]);
            float iA = sig_fast(acc[0][q]     + x0.x + bias2[0].x);
            float iB = sig_fast(acc[0][q + 1] + x0.y + bias2[0].y);
            float fA = sig_fast(acc[1][q]     + x1.x + bias2[1].x);
            float fB = sig_fast(acc[1][q + 1] + x1.y + bias2[1].y);
            float gA = tanh_fast(acc[2][q]     + x2.x + bias2[2].x);
            float gB = tanh_fast(acc[2][q + 1] + x2.y + bias2[2].y);
            float oA = sig_fast(acc[3][q]     + x3.x + bias2[3].x);
            float oB = sig_fast(acc[3][q + 1] + x3.y + bias2[3].y);
            int s = rs * 2;
            float cA = fmaf(fA, cst[s],     iA * gA);
            float cB = fmaf(fB, cst[s + 1], iB * gB);
            cst[s] = cA; cst[s + 1] = cB;
            float hA = oA * tanh_fast(cA);
            float hB = oB * tanh_fast(cB);
            hsum[s] += hA; hsum[s + 1] += hB;
            hv[rs] = pack_bf2(hA, hB);
        }
        // One STS.64: words (rs0,rs1) at this lane's frag quad
        {
            char* p = (char*)&hfq[nxt][kkp][lane] + wordoff;
            u64 pp;
            asm("mov.b64 %0, {%1, %2};" : "=l"(pp) : "r"(hv[0]), "r"(hv[1]));
            asm volatile("st.shared.b64 [%0], %1;"
                         :: "l"(__cvta_generic_to_shared(p)), "l"(pp) : "memory");
        }
        cur = nxt;
    }

#pragma unroll
    for (int rs = 0; rs < 2; rs++) {
        int b = b0 + t4 + 8 * rs;
        *(float2*)&g_rep[b * HH + colbase] = make_float2(hsum[rs * 2], hsum[rs * 2 + 1]);
    }
}

// ============================================================================
// Kernel 3: per-graph mean over cycles, classifier, log_softmax. Tiny.
// ============================================================================
__global__ void cls_kernel(const float* __restrict__ W_cls, const float* __restrict__ b_cls,
                           float* __restrict__ out) {
    __shared__ float mean_s[HH];
    __shared__ float lg[NCLASS];
    int g = blockIdx.x, tid = threadIdx.x;
    float s = 0.f;
    for (int c = 0; c < NC; c++)
        s += g_rep[(g * NC + c) * HH + tid];
    mean_s[tid] = s * (1.0f / NC);
    __syncthreads();
    if (tid < NCLASS) {
        float d = b_cls[tid];
        for (int h = 0; h < HH; h++)
            d = fmaf(mean_s[h], W_cls[tid * HH + h], d);
        lg[tid] = d;
    }
    __syncthreads();
    if (tid == 0) {
        float mx = lg[0];
        for (int n = 1; n < NCLASS; n++) mx = fmaxf(mx, lg[n]);
        float sum = 0.f;
        for (int n = 0; n < NCLASS; n++) sum += expf(lg[n] - mx);
        float l = logf(sum);
        for (int n = 0; n < NCLASS; n++)
            out[g * NCLASS + n] = lg[n] - mx - l;
    }
}

extern "C" void kernel_launch(void* const* d_in, const int* in_sizes, int n_in,
                              void* d_out, int out_size) {
    (void)in_sizes; (void)n_in; (void)out_size;
    const float* x     = (const float*)d_in[0];  // cycle_reps [64,32,128,64]
    const float* W_ih  = (const float*)d_in[1];  // [512,64]
    const float* W_hh  = (const float*)d_in[2];  // [512,128]
    const float* b_ih  = (const float*)d_in[3];  // [512]
    const float* b_hh  = (const float*)d_in[4];  // [512]
    const float* W_cls = (const float*)d_in[5];  // [10,128]
    const float* b_cls = (const float*)d_in[6];  // [10]

    cudaFuncSetAttribute(xg_mma_kernel, cudaFuncAttributeMaxDynamicSharedMemorySize, XSM_TOT);

    xg_mma_kernel<<<148, XTHREADS, XSM_TOT>>>(x, W_ih);
    lstm_kernel<<<128, LSTM_THREADS>>>(W_hh, b_ih, b_hh);
    cls_kernel<<<NG, HH>>>(W_cls, b_cls, (float*)d_out);
}

// round 9
// speedup vs baseline: 8.3149x; 1.6518x over previous
#include <cuda_runtime.h>
#include <cuda_bf16.h>
#include <cstdint>

#define NG 64
#define NC 32
#define LL 128
#define DD 64
#define HH 128
#define NCLASS 10
#define BTOT 2048          // G*C
#define NGATES 512         // 4*H

__device__ float g_rep[BTOT * HH];   // sum_t h (allocation-free scratch)

typedef unsigned long long u64;

__device__ __forceinline__ float tanh_fast(float x) {
    float r;
    asm("tanh.approx.f32 %0, %1;" : "=f"(r) : "f"(x));
    return r;
}
__device__ __forceinline__ float sig_fast(float x) {
    return fmaf(0.5f, tanh_fast(0.5f * x), 0.5f);
}
__device__ __forceinline__ uint32_t pack_bf2(float lo, float hi) {
    __nv_bfloat162 v = __floats2bfloat162_rn(lo, hi);   // .x = lo
    return *(uint32_t*)&v;
}

#define MMA_BF16(acc, a0, a1, a2, a3, bb0, bb1) \
    asm("mma.sync.aligned.m16n8k16.row.col.f32.bf16.bf16.f32 " \
        "{%0,%1,%2,%3}, {%4,%5,%6,%7}, {%8,%9}, {%0,%1,%2,%3};" \
        : "+f"((acc)[0]), "+f"((acc)[1]), "+f"((acc)[2]), "+f"((acc)[3]) \
        : "r"(a0), "r"(a1), "r"(a2), "r"(a3), "r"(bb0), "r"(bb1))

// ============================================================================
// Fused kernel: input GEMM + recurrent LSTM in one pass. 128 CTAs x 512
// threads; CTA owns 16 batches, all 512 gate-cols. Warp w (0..15) owns units
// 8w..8w+7 x 4 gates (4 n8-tiles). Per step, acc accumulates BOTH GEMMs:
//   acc = h_{t-1} @ W_hh^T  (8 k16 MMAs, A-frags from smem hfq, B in regs)
//       + x[:,t,:] @ W_ih^T (4 k16 MMAs, A-frags from smem xfq, B from smem)
// then bias + activations + c/h update, h stored back as A-fragment with one
// STS.64 (producer-lane == consumer-lane identity). x fragments are staged
// from gmem in 16-step chunks (double-buffered), coalesced LDG.128.
// No g_xg intermediate: DRAM traffic drops from ~600MB to 64MB.
// ============================================================================
#define LTH 512
#define HFQ_O 0                    // [2][8][32] uint4      (8 KB)
#define XFQ_O 512                  // [2][16][4][32] uint4  (64 KB)
#define WIFQ_O (512 + 4096)        // [16][4][2][32] uint4  (64 KB)
#define LSMQ (WIFQ_O + 4096)
#define LSM_BYTES (LSMQ * 16)      // 139264 B

__global__ void __launch_bounds__(LTH, 1)
lstm_fused(const float* __restrict__ x, const float* __restrict__ W_ih,
           const float* __restrict__ W_hh,
           const float* __restrict__ b_ih, const float* __restrict__ b_hh) {
    extern __shared__ uint4 smq[];
    uint4* hfq  = smq + HFQ_O;    // [(buf*8+kk)*32 + lane]
    uint4* xfq  = smq + XFQ_O;    // [((buf*16+tl)*4+kk2)*32 + lane]
    uint4* wifq = smq + WIFQ_O;   // [((w*4+kk2)*2+p)*32 + lane]

    int tid = threadIdx.x, lane = tid & 31, w = tid >> 5;   // w in [0,16)
    int t4 = lane >> 2, tm4 = lane & 3;
    int b0 = blockIdx.x * 16;
    int colbase = 8 * w + 2 * tm4;    // unit pair (colbase, colbase+1)

    // W_hh bf16 B-fragments -> registers (one-time). Frag col n = t4.
    uint32_t wb0[8][4], wb1[8][4];
#pragma unroll
    for (int kk = 0; kk < 8; kk++)
#pragma unroll
        for (int g = 0; g < 4; g++) {
            int row = g * HH + 8 * w + t4;
            float2 lo2 = *(const float2*)&W_hh[row * HH + kk * 16 + 2 * tm4];
            float2 hi2 = *(const float2*)&W_hh[row * HH + kk * 16 + 2 * tm4 + 8];
            wb0[kk][g] = pack_bf2(lo2.x, lo2.y);
            wb1[kk][g] = pack_bf2(hi2.x, hi2.y);
        }

    // W_ih bf16 B-fragments -> smem (warp-private region; K=64 -> 4 kk2)
#pragma unroll
    for (int kk2 = 0; kk2 < 4; kk2++) {
        uint32_t bb[4][2];
#pragma unroll
        for (int g = 0; g < 4; g++) {
            int row = g * HH + 8 * w + t4;
            float2 lo2 = *(const float2*)&W_ih[row * DD + kk2 * 16 + 2 * tm4];
            float2 hi2 = *(const float2*)&W_ih[row * DD + kk2 * 16 + 2 * tm4 + 8];
            bb[g][0] = pack_bf2(lo2.x, lo2.y);
            bb[g][1] = pack_bf2(hi2.x, hi2.y);
        }
        wifq[((w * 4 + kk2) * 2 + 0) * 32 + lane] =
            make_uint4(bb[0][0], bb[0][1], bb[1][0], bb[1][1]);
        wifq[((w * 4 + kk2) * 2 + 1) * 32 + lane] =
            make_uint4(bb[2][0], bb[2][1], bb[3][0], bb[3][1]);
    }
    // zero h fragments (both buffers): 512 entries, 512 threads
    hfq[tid] = make_uint4(0, 0, 0, 0);

    // Producer h-store coordinates (warp constants)
    const int kkp = w >> 1;
    const int wordoff = 8 * (w & 1);

    float2 bias2[4];
#pragma unroll
    for (int g = 0; g < 4; g++) {
        int c = g * HH + colbase;
        bias2[g] = make_float2(b_ih[c] + b_hh[c], b_ih[c + 1] + b_hh[c + 1]);
    }

    float cst[4], hsum[4];
#pragma unroll
    for (int k = 0; k < 4; k++) { cst[k] = 0.f; hsum[k] = 0.f; }

    // x chunk-staging coordinates (thread constants)
    const int s_tl = tid >> 5, s_kk2 = (tid >> 3) & 3, s_j = tid & 7;

    int cur = 0;
#pragma unroll 1
    for (int t = 0; t < LL; t++) {
        if ((t & 15) == 0) {
            // Stage x A-fragments for steps t..t+15 into buffer (t>>4)&1.
            // Thread: batch rows b0+s_j / b0+s_j+8, step t+s_tl, cols 16*s_kk2..+16.
            int cb = (t >> 4) & 1;
            const float* p0 = x + (((size_t)(b0 + s_j) * LL) + (t + s_tl)) * DD + s_kk2 * 16;
            const float* p1 = p0 + (size_t)8 * LL * DD;
            float4 r0a = *(const float4*)p0,       r0b = *(const float4*)(p0 + 4);
            float4 r0c = *(const float4*)(p0 + 8), r0d = *(const float4*)(p0 + 12);
            float4 r1a = *(const float4*)p1,       r1b = *(const float4*)(p1 + 4);
            float4 r1c = *(const float4*)(p1 + 8), r1d = *(const float4*)(p1 + 12);
            uint4* dst = &xfq[((cb * 16 + s_tl) * 4 + s_kk2) * 32 + 4 * s_j];
            dst[0] = make_uint4(pack_bf2(r0a.x, r0a.y), pack_bf2(r1a.x, r1a.y),
                                pack_bf2(r0c.x, r0c.y), pack_bf2(r1c.x, r1c.y));
            dst[1] = make_uint4(pack_bf2(r0a.z, r0a.w), pack_bf2(r1a.z, r1a.w),
                                pack_bf2(r0c.z, r0c.w), pack_bf2(r1c.z, r1c.w));
            dst[2] = make_uint4(pack_bf2(r0b.x, r0b.y), pack_bf2(r1b.x, r1b.y),
                                pack_bf2(r0d.x, r0d.y), pack_bf2(r1d.x, r1d.y));
            dst[3] = make_uint4(pack_bf2(r0b.z, r0b.w), pack_bf2(r1b.z, r1b.w),
                                pack_bf2(r0d.z, r0d.w), pack_bf2(r1d.z, r1d.w));
        }

        __syncthreads();   // h[cur] stores (prev step) + xfq chunk visible

        float acc[4][4];
#pragma unroll
        for (int g = 0; g < 4; g++)
#pragma unroll
            for (int q = 0; q < 4; q++) acc[g][q] = 0.f;

        // Recurrence: h_{t-1} @ W_hh^T
#pragma unroll
        for (int kk = 0; kk < 8; kk++) {
            uint4 aq = hfq[(cur * 8 + kk) * 32 + lane];
            MMA_BF16(acc[0], aq.x, aq.y, aq.z, aq.w, wb0[kk][0], wb1[kk][0]);
            MMA_BF16(acc[1], aq.x, aq.y, aq.z, aq.w, wb0[kk][1], wb1[kk][1]);
            MMA_BF16(acc[2], aq.x, aq.y, aq.z, aq.w, wb0[kk][2], wb1[kk][2]);
            MMA_BF16(acc[3], aq.x, aq.y, aq.z, aq.w, wb0[kk][3], wb1[kk][3]);
        }
        // Input GEMM: x[:,t,:] @ W_ih^T (fused into same accumulators)
        {
            int cb = (t >> 4) & 1, tl = t & 15;
#pragma unroll
            for (int kk2 = 0; kk2 < 4; kk2++) {
                uint4 aq = xfq[((cb * 16 + tl) * 4 + kk2) * 32 + lane];
                uint4 q0 = wifq[((w * 4 + kk2) * 2 + 0) * 32 + lane];
                uint4 q1 = wifq[((w * 4 + kk2) * 2 + 1) * 32 + lane];
                MMA_BF16(acc[0], aq.x, aq.y, aq.z, aq.w, q0.x, q0.y);
                MMA_BF16(acc[1], aq.x, aq.y, aq.z, aq.w, q0.z, q0.w);
                MMA_BF16(acc[2], aq.x, aq.y, aq.z, aq.w, q1.x, q1.y);
                MMA_BF16(acc[3], aq.x, aq.y, aq.z, aq.w, q1.z, q1.w);
            }
        }

        int nxt = cur ^ 1;
        uint32_t hv[2];
#pragma unroll
        for (int rs = 0; rs < 2; rs++) {
            int q = rs * 2;   // C-frag: q0,q1 = row t4 (batch b0+t4); q2,q3 = +8
            float iA = sig_fast(acc[0][q]     + bias2[0].x);
            float iB = sig_fast(acc[0][q + 1] + bias2[0].y);
            float fA = sig_fast(acc[1][q]     + bias2[1].x);
            float fB = sig_fast(acc[1][q + 1] + bias2[1].y);
            float gA = tanh_fast(acc[2][q]     + bias2[2].x);
            float gB = tanh_fast(acc[2][q + 1] + bias2[2].y);
            float oA = sig_fast(acc[3][q]     + bias2[3].x);
            float oB = sig_fast(acc[3][q + 1] + bias2[3].y);
            int s = rs * 2;
            float cA = fmaf(fA, cst[s],     iA * gA);
            float cB = fmaf(fB, cst[s + 1], iB * gB);
            cst[s] = cA; cst[s + 1] = cB;
            float hA = oA * tanh_fast(cA);
            float hB = oB * tanh_fast(cB);
            hsum[s] += hA; hsum[s + 1] += hB;
            hv[rs] = pack_bf2(hA, hB);
        }
        // One STS.64: this thread's h unit-pair, directly in A-fragment layout
        {
            char* p = (char*)&hfq[(nxt * 8 + kkp) * 32 + lane] + wordoff;
            u64 pp;
            asm("mov.b64 %0, {%1, %2};" : "=l"(pp) : "r"(hv[0]), "r"(hv[1]));
            asm volatile("st.shared.b64 [%0], %1;"
                         :: "l"(__cvta_generic_to_shared(p)), "l"(pp) : "memory");
        }
        cur = nxt;
    }

#pragma unroll
    for (int rs = 0; rs < 2; rs++) {
        int b = b0 + t4 + 8 * rs;
        *(float2*)&g_rep[b * HH + colbase] = make_float2(hsum[rs * 2], hsum[rs * 2 + 1]);
    }
}

// ============================================================================
// Kernel 2: per-graph mean over cycles, classifier, log_softmax. Tiny.
// ============================================================================
__global__ void cls_kernel(const float* __restrict__ W_cls, const float* __restrict__ b_cls,
                           float* __restrict__ out) {
    __shared__ float mean_s[HH];
    __shared__ float lg[NCLASS];
    int g = blockIdx.x, tid = threadIdx.x;
    float s = 0.f;
    for (int c = 0; c < NC; c++)
        s += g_rep[(g * NC + c) * HH + tid];
    mean_s[tid] = s * (1.0f / NC);
    __syncthreads();
    if (tid < NCLASS) {
        float d = b_cls[tid];
        for (int h = 0; h < HH; h++)
            d = fmaf(mean_s[h], W_cls[tid * HH + h], d);
        lg[tid] = d;
    }
    __syncthreads();
    if (tid == 0) {
        float mx = lg[0];
        for (int n = 1; n < NCLASS; n++) mx = fmaxf(mx, lg[n]);
        float sum = 0.f;
        for (int n = 0; n < NCLASS; n++) sum += expf(lg[n] - mx);
        float l = logf(sum);
        for (int n = 0; n < NCLASS; n++)
            out[g * NCLASS + n] = lg[n] - mx - l;
    }
}

extern "C" void kernel_launch(void* const* d_in, const int* in_sizes, int n_in,
                              void* d_out, int out_size) {
    (void)in_sizes; (void)n_in; (void)out_size;
    const float* x     = (const float*)d_in[0];  // cycle_reps [64,32,128,64]
    const float* W_ih  = (const float*)d_in[1];  // [512,64]
    const float* W_hh  = (const float*)d_in[2];  // [512,128]
    const float* b_ih  = (const float*)d_in[3];  // [512]
    const float* b_hh  = (const float*)d_in[4];  // [512]
    const float* W_cls = (const float*)d_in[5];  // [10,128]
    const float* b_cls = (const float*)d_in[6];  // [10]

    cudaFuncSetAttribute(lstm_fused, cudaFuncAttributeMaxDynamicSharedMemorySize, LSM_BYTES);
    lstm_fused<<<128, LTH, LSM_BYTES>>>(x, W_ih, W_hh, b_ih, b_hh);
    cls_kernel<<<NG, HH>>>(W_cls, b_cls, (float*)d_out);
}